// round 2
// baseline (speedup 1.0000x reference)
#include <cuda_runtime.h>
#include <math.h>

// Problem constants
#define D_MODEL   1024
#define NUM_HEADS 16
#define DK        64
#define BATCH     2
#define SEQ       2048
#define NROWS     (BATCH * SEQ)      // 4096

// ---------------------------------------------------------------------------
// Scratch (device globals: allocation-free rule)
// ---------------------------------------------------------------------------
__device__ float g_Q[BATCH * NUM_HEADS * SEQ * DK];   // [b][h][s][d]
__device__ float g_K[BATCH * NUM_HEADS * SEQ * DK];
__device__ float g_V[BATCH * NUM_HEADS * SEQ * DK];
__device__ float g_AO[BATCH * SEQ * D_MODEL];         // [b][s][h*64+d]

// ---------------------------------------------------------------------------
// GEMM: C = A (NR x K) * B (NC x K)^T, fp32, 128x128 block tile, 8x8/thread
// ---------------------------------------------------------------------------
#define GK 1024
#define BT 128
#define BK 16
#define SMSTRIDE 132   // padded row for transpose stores

// QKV projection: z selects W_{q,k,v}; epilogue scatters to head layout.
__global__ __launch_bounds__(256) void gemm_qkv(
    const float* __restrict__ x,
    const float* __restrict__ Wq,
    const float* __restrict__ Wk,
    const float* __restrict__ Wv)
{
    __shared__ float As[BK][SMSTRIDE];
    __shared__ float Bs[BK][SMSTRIDE];

    const float* W = (blockIdx.z == 0) ? Wq : (blockIdx.z == 1) ? Wk : Wv;
    float* dst = (blockIdx.z == 0) ? g_Q : (blockIdx.z == 1) ? g_K : g_V;

    int tid = threadIdx.x;
    int tc = tid & 15;
    int tr = tid >> 4;
    int rowBase = blockIdx.y * BT;
    int colBase = blockIdx.x * BT;

    const float* Ablk = x + (size_t)rowBase * GK;
    const float* Bblk = W + (size_t)colBase * GK;

    float acc[8][8];
#pragma unroll
    for (int i = 0; i < 8; i++)
#pragma unroll
        for (int j = 0; j < 8; j++) acc[i][j] = 0.f;

    for (int k0 = 0; k0 < GK; k0 += BK) {
#pragma unroll
        for (int u = 0; u < 2; u++) {
            int f  = tid * 2 + u;        // 0..511
            int r  = f >> 2;             // 0..127
            int c4 = (f & 3) << 2;       // 0,4,8,12
            float4 a = *(const float4*)(Ablk + r * GK + k0 + c4);
            As[c4 + 0][r] = a.x; As[c4 + 1][r] = a.y;
            As[c4 + 2][r] = a.z; As[c4 + 3][r] = a.w;
            float4 b = *(const float4*)(Bblk + r * GK + k0 + c4);
            Bs[c4 + 0][r] = b.x; Bs[c4 + 1][r] = b.y;
            Bs[c4 + 2][r] = b.z; Bs[c4 + 3][r] = b.w;
        }
        __syncthreads();
#pragma unroll
        for (int kk = 0; kk < BK; kk++) {
            float a[8], b[8];
            *(float4*)(a)     = *(float4*)&As[kk][tr * 8];
            *(float4*)(a + 4) = *(float4*)&As[kk][tr * 8 + 4];
            *(float4*)(b)     = *(float4*)&Bs[kk][tc * 8];
            *(float4*)(b + 4) = *(float4*)&Bs[kk][tc * 8 + 4];
#pragma unroll
            for (int i = 0; i < 8; i++)
#pragma unroll
                for (int j = 0; j < 8; j++)
                    acc[i][j] = fmaf(a[i], b[j], acc[i][j]);
        }
        __syncthreads();
    }

    // Epilogue: n=(b,s), m=(h,d). 8-col group never crosses a head (64%8==0).
    int col0 = colBase + tc * 8;
    int h = col0 >> 6;
    int d0 = col0 & 63;
#pragma unroll
    for (int i = 0; i < 8; i++) {
        int n = rowBase + tr * 8 + i;
        int b = n >> 11;         // /2048
        int s = n & 2047;
        float* p = dst + (((size_t)(b * NUM_HEADS + h) * SEQ + s) * DK + d0);
#pragma unroll
        for (int jj = 0; jj < 8; jj += 4) {
            float4 v = make_float4(acc[i][jj], acc[i][jj + 1], acc[i][jj + 2], acc[i][jj + 3]);
            *(float4*)(p + jj) = v;
        }
    }
}

// Output projection: out = g_AO (4096 x 1024) * Wo^T
__global__ __launch_bounds__(256) void gemm_oproj(
    const float* __restrict__ Wo, float* __restrict__ out)
{
    __shared__ float As[BK][SMSTRIDE];
    __shared__ float Bs[BK][SMSTRIDE];

    int tid = threadIdx.x;
    int tc = tid & 15;
    int tr = tid >> 4;
    int rowBase = blockIdx.y * BT;
    int colBase = blockIdx.x * BT;

    const float* Ablk = g_AO + (size_t)rowBase * GK;
    const float* Bblk = Wo + (size_t)colBase * GK;

    float acc[8][8];
#pragma unroll
    for (int i = 0; i < 8; i++)
#pragma unroll
        for (int j = 0; j < 8; j++) acc[i][j] = 0.f;

    for (int k0 = 0; k0 < GK; k0 += BK) {
#pragma unroll
        for (int u = 0; u < 2; u++) {
            int f  = tid * 2 + u;
            int r  = f >> 2;
            int c4 = (f & 3) << 2;
            float4 a = *(const float4*)(Ablk + r * GK + k0 + c4);
            As[c4 + 0][r] = a.x; As[c4 + 1][r] = a.y;
            As[c4 + 2][r] = a.z; As[c4 + 3][r] = a.w;
            float4 b = *(const float4*)(Bblk + r * GK + k0 + c4);
            Bs[c4 + 0][r] = b.x; Bs[c4 + 1][r] = b.y;
            Bs[c4 + 2][r] = b.z; Bs[c4 + 3][r] = b.w;
        }
        __syncthreads();
#pragma unroll
        for (int kk = 0; kk < BK; kk++) {
            float a[8], b[8];
            *(float4*)(a)     = *(float4*)&As[kk][tr * 8];
            *(float4*)(a + 4) = *(float4*)&As[kk][tr * 8 + 4];
            *(float4*)(b)     = *(float4*)&Bs[kk][tc * 8];
            *(float4*)(b + 4) = *(float4*)&Bs[kk][tc * 8 + 4];
#pragma unroll
            for (int i = 0; i < 8; i++)
#pragma unroll
                for (int j = 0; j < 8; j++)
                    acc[i][j] = fmaf(a[i], b[j], acc[i][j]);
        }
        __syncthreads();
    }

#pragma unroll
    for (int i = 0; i < 8; i++) {
        int n = rowBase + tr * 8 + i;
        float* p = out + (size_t)n * D_MODEL + colBase + tc * 8;
#pragma unroll
        for (int jj = 0; jj < 8; jj += 4) {
            float4 v = make_float4(acc[i][jj], acc[i][jj + 1], acc[i][jj + 2], acc[i][jj + 3]);
            *(float4*)(p + jj) = v;
        }
    }
}

// ---------------------------------------------------------------------------
// Flash attention (fp32 online softmax).
// Block: 256 threads (16x16), tile: 64 q-rows x 64 k-rows, dk=64.
// Smem operands stored transposed so every inner step is float4 LDS.
// ---------------------------------------------------------------------------
#define ATT_STRIDE 68                             // padded row (floats)
#define ATT_TILE   (64 * ATT_STRIDE)              // per-array floats
#define ATT_SMEM   (4 * ATT_TILE * (int)sizeof(float))  // 69632 bytes

__global__ __launch_bounds__(256) void flash_attn(const int* __restrict__ am)
{
    extern __shared__ float sm[];
    float* Qt = sm;                 // Qt[d][r], d=0..63 (dk), r=0..63 (q row)
    float* Kt = sm + ATT_TILE;      // Kt[d][c], c=key pos
    float* Vs = sm + 2 * ATT_TILE;  // Vs[c][d]
    float* Pt = sm + 3 * ATT_TILE;  // Pt[c][r]
    __shared__ int msk[64];

    int tid = threadIdx.x;
    int tx = tid & 15;              // col group
    int ty = tid >> 4;              // row group
    int q0 = blockIdx.x * 64;
    int h  = blockIdx.y;
    int b  = blockIdx.z;

    const float* Qg = g_Q + ((size_t)(b * NUM_HEADS + h) * SEQ) * DK;
    const float* Kg = g_K + ((size_t)(b * NUM_HEADS + h) * SEQ) * DK;
    const float* Vg = g_V + ((size_t)(b * NUM_HEADS + h) * SEQ) * DK;

    // Load Q tile (scaled by 1/sqrt(dk)=0.125), transposed.
    for (int u = tid; u < 64 * 16; u += 256) {
        int r  = u >> 4;
        int d4 = (u & 15) << 2;
        float4 q = *(const float4*)(Qg + (size_t)(q0 + r) * DK + d4);
        Qt[(d4 + 0) * ATT_STRIDE + r] = q.x * 0.125f;
        Qt[(d4 + 1) * ATT_STRIDE + r] = q.y * 0.125f;
        Qt[(d4 + 2) * ATT_STRIDE + r] = q.z * 0.125f;
        Qt[(d4 + 3) * ATT_STRIDE + r] = q.w * 0.125f;
    }

    float m[4], l[4], acc[4][4];
#pragma unroll
    for (int i = 0; i < 4; i++) {
        m[i] = -1e30f; l[i] = 0.f;
#pragma unroll
        for (int j = 0; j < 4; j++) acc[i][j] = 0.f;
    }

    for (int k0 = 0; k0 < SEQ; k0 += 64) {
        // Load K (transposed) and V tiles
        for (int u = tid; u < 64 * 16; u += 256) {
            int r  = u >> 4;
            int d4 = (u & 15) << 2;
            float4 k = *(const float4*)(Kg + (size_t)(k0 + r) * DK + d4);
            Kt[(d4 + 0) * ATT_STRIDE + r] = k.x;
            Kt[(d4 + 1) * ATT_STRIDE + r] = k.y;
            Kt[(d4 + 2) * ATT_STRIDE + r] = k.z;
            Kt[(d4 + 3) * ATT_STRIDE + r] = k.w;
            float4 v = *(const float4*)(Vg + (size_t)(k0 + r) * DK + d4);
            *(float4*)&Vs[r * ATT_STRIDE + d4] = v;
        }
        if (tid < 64) msk[tid] = am[(size_t)b * SEQ + k0 + tid];
        __syncthreads();

        // S = Q*K^T tile (rows ty*4.., cols tx*4..)
        float s[4][4];
#pragma unroll
        for (int i = 0; i < 4; i++)
#pragma unroll
            for (int j = 0; j < 4; j++) s[i][j] = 0.f;

#pragma unroll 16
        for (int kk = 0; kk < 64; kk++) {
            float4 qa = *(float4*)&Qt[kk * ATT_STRIDE + ty * 4];
            float4 kb = *(float4*)&Kt[kk * ATT_STRIDE + tx * 4];
            float a[4] = {qa.x, qa.y, qa.z, qa.w};
            float bb[4] = {kb.x, kb.y, kb.z, kb.w};
#pragma unroll
            for (int i = 0; i < 4; i++)
#pragma unroll
                for (int j = 0; j < 4; j++)
                    s[i][j] = fmaf(a[i], bb[j], s[i][j]);
        }

        // Mask
#pragma unroll
        for (int j = 0; j < 4; j++) {
            if (msk[tx * 4 + j] == 0) {
#pragma unroll
                for (int i = 0; i < 4; i++) s[i][j] = -1e30f;
            }
        }

        // Online softmax update
#pragma unroll
        for (int i = 0; i < 4; i++) {
            float mx = fmaxf(fmaxf(s[i][0], s[i][1]), fmaxf(s[i][2], s[i][3]));
#pragma unroll
            for (int o = 8; o >= 1; o >>= 1)
                mx = fmaxf(mx, __shfl_xor_sync(0xffffffffu, mx, o));
            float mnew = fmaxf(m[i], mx);
            float alpha = __expf(m[i] - mnew);
            float rs = 0.f;
#pragma unroll
            for (int j = 0; j < 4; j++) {
                s[i][j] = __expf(s[i][j] - mnew);   // now holds p
                rs += s[i][j];
            }
#pragma unroll
            for (int o = 8; o >= 1; o >>= 1)
                rs += __shfl_xor_sync(0xffffffffu, rs, o);
            l[i] = l[i] * alpha + rs;
            m[i] = mnew;
#pragma unroll
            for (int j = 0; j < 4; j++) acc[i][j] *= alpha;
        }

        // Write P transposed: Pt[keypos][qrow]
#pragma unroll
        for (int j = 0; j < 4; j++)
#pragma unroll
            for (int i = 0; i < 4; i++)
                Pt[(tx * 4 + j) * ATT_STRIDE + ty * 4 + i] = s[i][j];
        __syncthreads();

        // O += P * V  (rows=q rows ty*4.., cols=dk dims tx*4..)
#pragma unroll 16
        for (int kk = 0; kk < 64; kk++) {
            float4 pa = *(float4*)&Pt[kk * ATT_STRIDE + ty * 4];
            float4 vb = *(float4*)&Vs[kk * ATT_STRIDE + tx * 4];
            float p[4] = {pa.x, pa.y, pa.z, pa.w};
            float v[4] = {vb.x, vb.y, vb.z, vb.w};
#pragma unroll
            for (int i = 0; i < 4; i++)
#pragma unroll
                for (int j = 0; j < 4; j++)
                    acc[i][j] = fmaf(p[i], v[j], acc[i][j]);
        }
        __syncthreads();   // protect Kt/Vs/Pt before next tile's writes
    }

    // Normalize and write to [b][s][h*64+d]
#pragma unroll
    for (int i = 0; i < 4; i++) {
        float inv = (l[i] > 0.f) ? (1.f / l[i]) : 0.f;
        float4 o = make_float4(acc[i][0] * inv, acc[i][1] * inv,
                               acc[i][2] * inv, acc[i][3] * inv);
        size_t idx = ((size_t)b * SEQ + q0 + ty * 4 + i) * D_MODEL + h * DK + tx * 4;
        *(float4*)&g_AO[idx] = o;
    }
}

// ---------------------------------------------------------------------------
// Launch
// ---------------------------------------------------------------------------
extern "C" void kernel_launch(void* const* d_in, const int* in_sizes, int n_in,
                              void* d_out, int out_size)
{
    const float* x  = (const float*)d_in[0];
    const int*   am = (const int*)d_in[1];
    const float* Wq = (const float*)d_in[2];
    const float* Wk = (const float*)d_in[3];
    const float* Wv = (const float*)d_in[4];
    const float* Wo = (const float*)d_in[5];
    float* out = (float*)d_out;

    cudaFuncSetAttribute(flash_attn, cudaFuncAttributeMaxDynamicSharedMemorySize, ATT_SMEM);

    dim3 gq(D_MODEL / BT, NROWS / BT, 3);       // (8, 32, 3)
    gemm_qkv<<<gq, 256>>>(x, Wq, Wk, Wv);

    dim3 ga(SEQ / 64, NUM_HEADS, BATCH);        // (32, 16, 2)
    flash_attn<<<ga, 256, ATT_SMEM>>>(am);

    dim3 go(D_MODEL / BT, NROWS / BT);          // (8, 32)
    gemm_oproj<<<go, 256>>>(Wo, out);
}

// round 5
// speedup vs baseline: 1.3656x; 1.3656x over previous
#include <cuda_runtime.h>
#include <cuda_bf16.h>
#include <cstdint>
#include <math.h>

// Problem constants
#define D_MODEL   1024
#define NUM_HEADS 16
#define DK        64
#define BATCH     2
#define SEQ       2048
#define NROWS     (BATCH * SEQ)      // 4096
#define NX        (NROWS * D_MODEL)  // 4194304
#define NW        (D_MODEL * D_MODEL)// 1048576

// ---------------------------------------------------------------------------
// Scratch (device globals: allocation-free rule)
// ---------------------------------------------------------------------------
__device__ float g_Q[BATCH * NUM_HEADS * SEQ * DK];   // [b][h][s][d] fp32
__device__ float g_K[BATCH * NUM_HEADS * SEQ * DK];
__device__ float g_V[BATCH * NUM_HEADS * SEQ * DK];
__device__ __nv_bfloat16 g_xh[NX],  g_xl[NX];         // x split hi/lo
__device__ __nv_bfloat16 g_Wh[4 * NW], g_Wl[4 * NW];  // Wq,Wk,Wv,Wo split
__device__ __nv_bfloat16 g_AOh[NX], g_AOl[NX];        // attn out split [b][s][h*64+d]

// ---------------------------------------------------------------------------
// PTX helpers (plain sm_100-safe: ldmatrix sm_75+, mma.sync bf16 sm_80+)
// ---------------------------------------------------------------------------
__device__ __forceinline__ uint32_t smem_to_u32(const void* p) {
    uint32_t a;
    asm("{ .reg .u64 t; cvta.to.shared.u64 t, %1; cvt.u32.u64 %0, t; }" : "=r"(a) : "l"(p));
    return a;
}
__device__ __forceinline__ void ldsm_x4(uint32_t* r, uint32_t addr) {
    asm volatile("ldmatrix.sync.aligned.m8n8.x4.shared.b16 {%0,%1,%2,%3}, [%4];"
        : "=r"(r[0]), "=r"(r[1]), "=r"(r[2]), "=r"(r[3]) : "r"(addr));
}
__device__ __forceinline__ void mma_bf16(float* d, const uint32_t* a, uint32_t b0, uint32_t b1) {
    asm volatile("mma.sync.aligned.m16n8k16.row.col.f32.bf16.bf16.f32 "
        "{%0,%1,%2,%3}, {%4,%5,%6,%7}, {%8,%9}, {%0,%1,%2,%3};"
        : "+f"(d[0]), "+f"(d[1]), "+f"(d[2]), "+f"(d[3])
        : "r"(a[0]), "r"(a[1]), "r"(a[2]), "r"(a[3]), "r"(b0), "r"(b1));
}
__device__ __forceinline__ uint32_t pack_bf16(__nv_bfloat16 a, __nv_bfloat16 b) {
    __nv_bfloat162 t = __halves2bfloat162(a, b);
    return *(uint32_t*)&t;
}

// ---------------------------------------------------------------------------
// Pre-pass: split-convert x + 4 weights to bf16 hi/lo (one shot)
// grid (1024, 5): y=0 -> x (4M elems, 4 iters), y=1..4 -> Wq/Wk/Wv/Wo (1M)
// ---------------------------------------------------------------------------
__global__ __launch_bounds__(256) void cvt_all(
    const float* __restrict__ x,  const float* __restrict__ wq,
    const float* __restrict__ wk, const float* __restrict__ wv,
    const float* __restrict__ wo)
{
    int y = blockIdx.y;
    const float* s = (y == 0) ? x : (y == 1) ? wq : (y == 2) ? wk : (y == 3) ? wv : wo;
    __nv_bfloat16* dh = (y == 0) ? g_xh : g_Wh + (size_t)(y - 1) * NW;
    __nv_bfloat16* dl = (y == 0) ? g_xl : g_Wl + (size_t)(y - 1) * NW;
    size_t n = (y == 0) ? (size_t)NX : (size_t)NW;
    size_t stride = (size_t)gridDim.x * 256 * 4;
    for (size_t i = ((size_t)blockIdx.x * 256 + threadIdx.x) * 4; i < n; i += stride) {
        float4 v = *(const float4*)(s + i);
        float f[4] = {v.x, v.y, v.z, v.w};
        __nv_bfloat16 h[4], l[4];
#pragma unroll
        for (int e = 0; e < 4; e++) {
            h[e] = __float2bfloat16(f[e]);
            l[e] = __float2bfloat16(f[e] - __bfloat162float(h[e]));
        }
        *(uint2*)(dh + i) = make_uint2(pack_bf16(h[0], h[1]), pack_bf16(h[2], h[3]));
        *(uint2*)(dl + i) = make_uint2(pack_bf16(l[0], l[1]), pack_bf16(l[2], l[3]));
    }
}

// ---------------------------------------------------------------------------
// Split-bf16 tensor-core GEMM: C[4096x1024] = A @ W^T
// CTA 128x128, 8 warps (2m x 4n), warp tile 64x32, k-stage 32 (2 k16 steps).
// Smem rows padded to 40 bf16 (80B) -> conflict-free ldmatrix.
// D += Ah*Bh + Ah*Bl + Al*Bh  (3 mma.sync per 16x8 tile per k16)
// MODE 0: QKV (z selects W; head-scatter f32 epilogue to g_Q/K/V)
// MODE 1: O-proj (A = g_AOh/l; plain f32 epilogue to out)
// ---------------------------------------------------------------------------
#define SSTR 40                       // smem row stride in bf16
#define SSTRB 80                      // ... in bytes
#define TILE_HALF (128 * SSTR)        // bf16 elems per tile array

template<int MODE>
__global__ __launch_bounds__(256) void gemm_mma(float* __restrict__ outp)
{
    __shared__ __nv_bfloat16 sAh[TILE_HALF], sAl[TILE_HALF], sBh[TILE_HALF], sBl[TILE_HALF];

    int tid = threadIdx.x;
    int wid = tid >> 5, lane = tid & 31;
    int wm = wid & 1, wn = wid >> 1;          // warp grid 2x4
    int rowBase = blockIdx.y * 128, colBase = blockIdx.x * 128;

    const __nv_bfloat16 *Ahg, *Alg, *Bhg, *Blg;
    if (MODE == 0) {
        int z = blockIdx.z;
        Ahg = g_xh;  Alg = g_xl;
        Bhg = g_Wh + (size_t)z * NW;  Blg = g_Wl + (size_t)z * NW;
    } else {
        Ahg = g_AOh; Alg = g_AOl;
        Bhg = g_Wh + 3ull * NW;       Blg = g_Wl + 3ull * NW;
    }
    Ahg += (size_t)rowBase * D_MODEL;  Alg += (size_t)rowBase * D_MODEL;
    Bhg += (size_t)colBase * D_MODEL;  Blg += (size_t)colBase * D_MODEL;

    float acc[4][4][4];
#pragma unroll
    for (int i = 0; i < 4; i++)
#pragma unroll
        for (int j = 0; j < 4; j++)
#pragma unroll
            for (int c = 0; c < 4; c++) acc[i][j][c] = 0.f;

    // ldmatrix per-thread addresses
    uint32_t uAh = smem_to_u32(sAh), uAl = smem_to_u32(sAl);
    uint32_t uBh = smem_to_u32(sBh), uBl = smem_to_u32(sBl);
    uint32_t aOff = (uint32_t)((wm * 64 + (lane & 15)) * SSTRB + (lane >> 4) * 16);
    uint32_t bOff = (uint32_t)((wn * 32 + (lane & 7) + ((lane >> 4) & 1) * 8) * SSTRB
                               + ((lane >> 3) & 1) * 16);

    // gmem prefetch regs: per array, 2 x uint4 (8 bf16 each)
    uint4 pAh[2], pAl[2], pBh[2], pBl[2];
#pragma unroll
    for (int u = 0; u < 2; u++) {
        int f = tid + 256 * u;
        int row = f >> 2, seg = (f & 3) * 8;
        size_t g = (size_t)row * D_MODEL + seg;
        pAh[u] = *(const uint4*)(Ahg + g);  pAl[u] = *(const uint4*)(Alg + g);
        pBh[u] = *(const uint4*)(Bhg + g);  pBl[u] = *(const uint4*)(Blg + g);
    }

    for (int st = 0; st < D_MODEL / 32; st++) {
#pragma unroll
        for (int u = 0; u < 2; u++) {
            int f = tid + 256 * u;
            int row = f >> 2, seg = (f & 3) * 8;
            int so = row * SSTR + seg;
            *(uint4*)(sAh + so) = pAh[u];  *(uint4*)(sAl + so) = pAl[u];
            *(uint4*)(sBh + so) = pBh[u];  *(uint4*)(sBl + so) = pBl[u];
        }
        __syncthreads();

        if (st < D_MODEL / 32 - 1) {
            int k0 = (st + 1) * 32;
#pragma unroll
            for (int u = 0; u < 2; u++) {
                int f = tid + 256 * u;
                int row = f >> 2, seg = (f & 3) * 8;
                size_t g = (size_t)row * D_MODEL + k0 + seg;
                pAh[u] = *(const uint4*)(Ahg + g);  pAl[u] = *(const uint4*)(Alg + g);
                pBh[u] = *(const uint4*)(Bhg + g);  pBl[u] = *(const uint4*)(Blg + g);
            }
        }

#pragma unroll
        for (int ks = 0; ks < 2; ks++) {
            uint32_t kb = (uint32_t)(ks * 32);     // 16 bf16 = 32 bytes
            uint32_t ah[4][4], al[4][4];
#pragma unroll
            for (int mt = 0; mt < 4; mt++) {
                uint32_t o = aOff + mt * 16 * SSTRB + kb;
                ldsm_x4(ah[mt], uAh + o);
                ldsm_x4(al[mt], uAl + o);
            }
            uint32_t bh[2][4], bl[2][4];
#pragma unroll
            for (int p = 0; p < 2; p++) {
                uint32_t o = bOff + p * 16 * SSTRB + kb;
                ldsm_x4(bh[p], uBh + o);
                ldsm_x4(bl[p], uBl + o);
            }
#pragma unroll
            for (int mt = 0; mt < 4; mt++)
#pragma unroll
                for (int nt = 0; nt < 4; nt++) {
                    int p = nt >> 1, q = (nt & 1) * 2;
                    mma_bf16(acc[mt][nt], ah[mt], bh[p][q], bh[p][q + 1]);
                    mma_bf16(acc[mt][nt], ah[mt], bl[p][q], bl[p][q + 1]);
                    mma_bf16(acc[mt][nt], al[mt], bh[p][q], bh[p][q + 1]);
                }
        }
        __syncthreads();
    }

    // Epilogue: thread (lane) holds C[r][c],C[r][c+1] (c0,c1) and C[r+8][..] (c2,c3)
#pragma unroll
    for (int mt = 0; mt < 4; mt++)
#pragma unroll
        for (int nt = 0; nt < 4; nt++) {
            int row0 = rowBase + wm * 64 + mt * 16 + (lane >> 2);
            int col  = colBase + wn * 32 + nt * 8 + (lane & 3) * 2;
#pragma unroll
            for (int cp = 0; cp < 2; cp++) {
                int row = row0 + cp * 8;
                float2 v = make_float2(acc[mt][nt][cp * 2], acc[mt][nt][cp * 2 + 1]);
                if (MODE == 1) {
                    *(float2*)(outp + (size_t)row * D_MODEL + col) = v;
                } else {
                    float* dst = (blockIdx.z == 0) ? g_Q : (blockIdx.z == 1) ? g_K : g_V;
                    int b = row >> 11, s = row & 2047;
                    int h = col >> 6, d = col & 63;
                    *(float2*)(dst + (((size_t)(b * NUM_HEADS + h) * SEQ + s) * DK + d)) = v;
                }
            }
        }
}

// ---------------------------------------------------------------------------
// Flash attention (fp32 online softmax) — epilogue now emits bf16 hi/lo AO.
// ---------------------------------------------------------------------------
#define ATT_STRIDE 68
#define ATT_TILE   (64 * ATT_STRIDE)
#define ATT_SMEM   (4 * ATT_TILE * (int)sizeof(float))  // 69632 bytes

__global__ __launch_bounds__(256) void flash_attn(const int* __restrict__ am)
{
    extern __shared__ float sm[];
    float* Qt = sm;
    float* Kt = sm + ATT_TILE;
    float* Vs = sm + 2 * ATT_TILE;
    float* Pt = sm + 3 * ATT_TILE;
    __shared__ int msk[64];

    int tid = threadIdx.x;
    int tx = tid & 15;
    int ty = tid >> 4;
    int q0 = blockIdx.x * 64;
    int h  = blockIdx.y;
    int b  = blockIdx.z;

    const float* Qg = g_Q + ((size_t)(b * NUM_HEADS + h) * SEQ) * DK;
    const float* Kg = g_K + ((size_t)(b * NUM_HEADS + h) * SEQ) * DK;
    const float* Vg = g_V + ((size_t)(b * NUM_HEADS + h) * SEQ) * DK;

    for (int u = tid; u < 64 * 16; u += 256) {
        int r  = u >> 4;
        int d4 = (u & 15) << 2;
        float4 q = *(const float4*)(Qg + (size_t)(q0 + r) * DK + d4);
        Qt[(d4 + 0) * ATT_STRIDE + r] = q.x * 0.125f;
        Qt[(d4 + 1) * ATT_STRIDE + r] = q.y * 0.125f;
        Qt[(d4 + 2) * ATT_STRIDE + r] = q.z * 0.125f;
        Qt[(d4 + 3) * ATT_STRIDE + r] = q.w * 0.125f;
    }

    float m[4], l[4], acc[4][4];
#pragma unroll
    for (int i = 0; i < 4; i++) {
        m[i] = -1e30f; l[i] = 0.f;
#pragma unroll
        for (int j = 0; j < 4; j++) acc[i][j] = 0.f;
    }

    for (int k0 = 0; k0 < SEQ; k0 += 64) {
        for (int u = tid; u < 64 * 16; u += 256) {
            int r  = u >> 4;
            int d4 = (u & 15) << 2;
            float4 k = *(const float4*)(Kg + (size_t)(k0 + r) * DK + d4);
            Kt[(d4 + 0) * ATT_STRIDE + r] = k.x;
            Kt[(d4 + 1) * ATT_STRIDE + r] = k.y;
            Kt[(d4 + 2) * ATT_STRIDE + r] = k.z;
            Kt[(d4 + 3) * ATT_STRIDE + r] = k.w;
            float4 v = *(const float4*)(Vg + (size_t)(k0 + r) * DK + d4);
            *(float4*)&Vs[r * ATT_STRIDE + d4] = v;
        }
        if (tid < 64) msk[tid] = am[(size_t)b * SEQ + k0 + tid];
        __syncthreads();

        float s[4][4];
#pragma unroll
        for (int i = 0; i < 4; i++)
#pragma unroll
            for (int j = 0; j < 4; j++) s[i][j] = 0.f;

#pragma unroll 16
        for (int kk = 0; kk < 64; kk++) {
            float4 qa = *(float4*)&Qt[kk * ATT_STRIDE + ty * 4];
            float4 kb = *(float4*)&Kt[kk * ATT_STRIDE + tx * 4];
            float a[4] = {qa.x, qa.y, qa.z, qa.w};
            float bb[4] = {kb.x, kb.y, kb.z, kb.w};
#pragma unroll
            for (int i = 0; i < 4; i++)
#pragma unroll
                for (int j = 0; j < 4; j++)
                    s[i][j] = fmaf(a[i], bb[j], s[i][j]);
        }

#pragma unroll
        for (int j = 0; j < 4; j++) {
            if (msk[tx * 4 + j] == 0) {
#pragma unroll
                for (int i = 0; i < 4; i++) s[i][j] = -1e30f;
            }
        }

#pragma unroll
        for (int i = 0; i < 4; i++) {
            float mx = fmaxf(fmaxf(s[i][0], s[i][1]), fmaxf(s[i][2], s[i][3]));
#pragma unroll
            for (int o = 8; o >= 1; o >>= 1)
                mx = fmaxf(mx, __shfl_xor_sync(0xffffffffu, mx, o));
            float mnew = fmaxf(m[i], mx);
            float alpha = __expf(m[i] - mnew);
            float rs = 0.f;
#pragma unroll
            for (int j = 0; j < 4; j++) {
                s[i][j] = __expf(s[i][j] - mnew);
                rs += s[i][j];
            }
#pragma unroll
            for (int o = 8; o >= 1; o >>= 1)
                rs += __shfl_xor_sync(0xffffffffu, rs, o);
            l[i] = l[i] * alpha + rs;
            m[i] = mnew;
#pragma unroll
            for (int j = 0; j < 4; j++) acc[i][j] *= alpha;
        }

#pragma unroll
        for (int j = 0; j < 4; j++)
#pragma unroll
            for (int i = 0; i < 4; i++)
                Pt[(tx * 4 + j) * ATT_STRIDE + ty * 4 + i] = s[i][j];
        __syncthreads();

#pragma unroll 16
        for (int kk = 0; kk < 64; kk++) {
            float4 pa = *(float4*)&Pt[kk * ATT_STRIDE + ty * 4];
            float4 vb = *(float4*)&Vs[kk * ATT_STRIDE + tx * 4];
            float p[4] = {pa.x, pa.y, pa.z, pa.w};
            float v[4] = {vb.x, vb.y, vb.z, vb.w};
#pragma unroll
            for (int i = 0; i < 4; i++)
#pragma unroll
                for (int j = 0; j < 4; j++)
                    acc[i][j] = fmaf(p[i], v[j], acc[i][j]);
        }
        __syncthreads();
    }

    // Normalize and write split-bf16 AO to [b][s][h*64+d]
#pragma unroll
    for (int i = 0; i < 4; i++) {
        float inv = (l[i] > 0.f) ? (1.f / l[i]) : 0.f;
        float o[4];
        __nv_bfloat16 oh[4], ol[4];
#pragma unroll
        for (int j = 0; j < 4; j++) {
            o[j] = acc[i][j] * inv;
            oh[j] = __float2bfloat16(o[j]);
            ol[j] = __float2bfloat16(o[j] - __bfloat162float(oh[j]));
        }
        size_t idx = ((size_t)b * SEQ + q0 + ty * 4 + i) * D_MODEL + h * DK + tx * 4;
        *(uint2*)(g_AOh + idx) = make_uint2(pack_bf16(oh[0], oh[1]), pack_bf16(oh[2], oh[3]));
        *(uint2*)(g_AOl + idx) = make_uint2(pack_bf16(ol[0], ol[1]), pack_bf16(ol[2], ol[3]));
    }
}

// ---------------------------------------------------------------------------
// Launch
// ---------------------------------------------------------------------------
extern "C" void kernel_launch(void* const* d_in, const int* in_sizes, int n_in,
                              void* d_out, int out_size)
{
    const float* x  = (const float*)d_in[0];
    const int*   am = (const int*)d_in[1];
    const float* Wq = (const float*)d_in[2];
    const float* Wk = (const float*)d_in[3];
    const float* Wv = (const float*)d_in[4];
    const float* Wo = (const float*)d_in[5];
    float* out = (float*)d_out;

    cudaFuncSetAttribute(flash_attn, cudaFuncAttributeMaxDynamicSharedMemorySize, ATT_SMEM);

    dim3 gc(1024, 5);
    cvt_all<<<gc, 256>>>(x, Wq, Wk, Wv, Wo);

    dim3 gq(D_MODEL / 128, NROWS / 128, 3);     // (8, 32, 3)
    gemm_mma<0><<<gq, 256>>>(nullptr);

    dim3 ga(SEQ / 64, NUM_HEADS, BATCH);        // (32, 16, 2)
    flash_attn<<<ga, 256, ATT_SMEM>>>(am);

    dim3 go(D_MODEL / 128, NROWS / 128, 1);     // (8, 32)
    gemm_mma<1><<<go, 256>>>(out);
}

// round 7
// speedup vs baseline: 2.4849x; 1.8197x over previous
#include <cuda_runtime.h>
#include <cuda_bf16.h>
#include <cstdint>
#include <math.h>

// Problem constants
#define D_MODEL   1024
#define NUM_HEADS 16
#define DK        64
#define BATCH     2
#define SEQ       2048
#define NROWS     (BATCH * SEQ)      // 4096
#define NX        (NROWS * D_MODEL)  // 4194304
#define NW        (D_MODEL * D_MODEL)// 1048576

// ---------------------------------------------------------------------------
// Scratch (device globals: allocation-free rule)
// ---------------------------------------------------------------------------
__device__ __nv_bfloat16 g_xh[NX],  g_xl[NX];         // x split hi/lo
__device__ __nv_bfloat16 g_Wh[4 * NW], g_Wl[4 * NW];  // Wq,Wk,Wv,Wo split
__device__ __nv_bfloat16 g_Qh[NX], g_Ql[NX];          // [b][h][s][d], pre-scaled 0.125
__device__ __nv_bfloat16 g_Kh[NX], g_Kl[NX];
__device__ __nv_bfloat16 g_Vh[NX], g_Vl[NX];
__device__ __nv_bfloat16 g_AOh[NX], g_AOl[NX];        // attn out split [b][s][h*64+d]

// ---------------------------------------------------------------------------
// PTX helpers (plain sm_100-safe: ldmatrix sm_75+, mma.sync bf16 sm_80+)
// ---------------------------------------------------------------------------
__device__ __forceinline__ uint32_t smem_to_u32(const void* p) {
    uint32_t a;
    asm("{ .reg .u64 t; cvta.to.shared.u64 t, %1; cvt.u32.u64 %0, t; }" : "=r"(a) : "l"(p));
    return a;
}
__device__ __forceinline__ void ldsm_x4(uint32_t* r, uint32_t addr) {
    asm volatile("ldmatrix.sync.aligned.m8n8.x4.shared.b16 {%0,%1,%2,%3}, [%4];"
        : "=r"(r[0]), "=r"(r[1]), "=r"(r[2]), "=r"(r[3]) : "r"(addr));
}
__device__ __forceinline__ void ldsm_x4_t(uint32_t* r, uint32_t addr) {
    asm volatile("ldmatrix.sync.aligned.m8n8.x4.trans.shared.b16 {%0,%1,%2,%3}, [%4];"
        : "=r"(r[0]), "=r"(r[1]), "=r"(r[2]), "=r"(r[3]) : "r"(addr));
}
__device__ __forceinline__ void mma_bf16(float* d, const uint32_t* a, uint32_t b0, uint32_t b1) {
    asm volatile("mma.sync.aligned.m16n8k16.row.col.f32.bf16.bf16.f32 "
        "{%0,%1,%2,%3}, {%4,%5,%6,%7}, {%8,%9}, {%0,%1,%2,%3};"
        : "+f"(d[0]), "+f"(d[1]), "+f"(d[2]), "+f"(d[3])
        : "r"(a[0]), "r"(a[1]), "r"(a[2]), "r"(a[3]), "r"(b0), "r"(b1));
}
__device__ __forceinline__ uint32_t pack_bf16(__nv_bfloat16 a, __nv_bfloat16 b) {
    __nv_bfloat162 t = __halves2bfloat162(a, b);
    return *(uint32_t*)&t;
}
__device__ __forceinline__ uint32_t split_pack_hi(float v0, float v1,
                                                  __nv_bfloat16& h0, __nv_bfloat16& h1) {
    h0 = __float2bfloat16(v0);
    h1 = __float2bfloat16(v1);
    return pack_bf16(h0, h1);
}

// ---------------------------------------------------------------------------
// Pre-pass: split-convert x + 4 weights to bf16 hi/lo (one shot)
// ---------------------------------------------------------------------------
__global__ __launch_bounds__(256) void cvt_all(
    const float* __restrict__ x,  const float* __restrict__ wq,
    const float* __restrict__ wk, const float* __restrict__ wv,
    const float* __restrict__ wo)
{
    int y = blockIdx.y;
    const float* s = (y == 0) ? x : (y == 1) ? wq : (y == 2) ? wk : (y == 3) ? wv : wo;
    __nv_bfloat16* dh = (y == 0) ? g_xh : g_Wh + (size_t)(y - 1) * NW;
    __nv_bfloat16* dl = (y == 0) ? g_xl : g_Wl + (size_t)(y - 1) * NW;
    size_t n = (y == 0) ? (size_t)NX : (size_t)NW;
    size_t stride = (size_t)gridDim.x * 256 * 4;
    for (size_t i = ((size_t)blockIdx.x * 256 + threadIdx.x) * 4; i < n; i += stride) {
        float4 v = *(const float4*)(s + i);
        float f[4] = {v.x, v.y, v.z, v.w};
        __nv_bfloat16 h[4], l[4];
#pragma unroll
        for (int e = 0; e < 4; e++) {
            h[e] = __float2bfloat16(f[e]);
            l[e] = __float2bfloat16(f[e] - __bfloat162float(h[e]));
        }
        *(uint2*)(dh + i) = make_uint2(pack_bf16(h[0], h[1]), pack_bf16(h[2], h[3]));
        *(uint2*)(dl + i) = make_uint2(pack_bf16(l[0], l[1]), pack_bf16(l[2], l[3]));
    }
}

// ---------------------------------------------------------------------------
// Split-bf16 tensor-core GEMM: C[4096x1024] = A @ W^T
// MODE 0: QKV (z selects W; epilogue -> bf16 hi/lo head-scatter, Q scaled 0.125)
// MODE 1: O-proj (A = g_AOh/l; fp32 epilogue to out)
// ---------------------------------------------------------------------------
#define SSTR 40                       // smem row stride in bf16
#define SSTRB 80
#define TILE_HALF (128 * SSTR)

template<int MODE>
__global__ __launch_bounds__(256) void gemm_mma(float* __restrict__ outp)
{
    __shared__ __nv_bfloat16 sAh[TILE_HALF], sAl[TILE_HALF], sBh[TILE_HALF], sBl[TILE_HALF];

    int tid = threadIdx.x;
    int wid = tid >> 5, lane = tid & 31;
    int wm = wid & 1, wn = wid >> 1;
    int rowBase = blockIdx.y * 128, colBase = blockIdx.x * 128;

    const __nv_bfloat16 *Ahg, *Alg, *Bhg, *Blg;
    if (MODE == 0) {
        int z = blockIdx.z;
        Ahg = g_xh;  Alg = g_xl;
        Bhg = g_Wh + (size_t)z * NW;  Blg = g_Wl + (size_t)z * NW;
    } else {
        Ahg = g_AOh; Alg = g_AOl;
        Bhg = g_Wh + 3ull * NW;       Blg = g_Wl + 3ull * NW;
    }
    Ahg += (size_t)rowBase * D_MODEL;  Alg += (size_t)rowBase * D_MODEL;
    Bhg += (size_t)colBase * D_MODEL;  Blg += (size_t)colBase * D_MODEL;

    float acc[4][4][4];
#pragma unroll
    for (int i = 0; i < 4; i++)
#pragma unroll
        for (int j = 0; j < 4; j++)
#pragma unroll
            for (int c = 0; c < 4; c++) acc[i][j][c] = 0.f;

    uint32_t uAh = smem_to_u32(sAh), uAl = smem_to_u32(sAl);
    uint32_t uBh = smem_to_u32(sBh), uBl = smem_to_u32(sBl);
    uint32_t aOff = (uint32_t)((wm * 64 + (lane & 15)) * SSTRB + (lane >> 4) * 16);
    uint32_t bOff = (uint32_t)((wn * 32 + (lane & 7) + ((lane >> 4) & 1) * 8) * SSTRB
                               + ((lane >> 3) & 1) * 16);

    uint4 pAh[2], pAl[2], pBh[2], pBl[2];
#pragma unroll
    for (int u = 0; u < 2; u++) {
        int f = tid + 256 * u;
        int row = f >> 2, seg = (f & 3) * 8;
        size_t g = (size_t)row * D_MODEL + seg;
        pAh[u] = *(const uint4*)(Ahg + g);  pAl[u] = *(const uint4*)(Alg + g);
        pBh[u] = *(const uint4*)(Bhg + g);  pBl[u] = *(const uint4*)(Blg + g);
    }

    for (int st = 0; st < D_MODEL / 32; st++) {
#pragma unroll
        for (int u = 0; u < 2; u++) {
            int f = tid + 256 * u;
            int row = f >> 2, seg = (f & 3) * 8;
            int so = row * SSTR + seg;
            *(uint4*)(sAh + so) = pAh[u];  *(uint4*)(sAl + so) = pAl[u];
            *(uint4*)(sBh + so) = pBh[u];  *(uint4*)(sBl + so) = pBl[u];
        }
        __syncthreads();

        if (st < D_MODEL / 32 - 1) {
            int k0 = (st + 1) * 32;
#pragma unroll
            for (int u = 0; u < 2; u++) {
                int f = tid + 256 * u;
                int row = f >> 2, seg = (f & 3) * 8;
                size_t g = (size_t)row * D_MODEL + k0 + seg;
                pAh[u] = *(const uint4*)(Ahg + g);  pAl[u] = *(const uint4*)(Alg + g);
                pBh[u] = *(const uint4*)(Bhg + g);  pBl[u] = *(const uint4*)(Blg + g);
            }
        }

#pragma unroll
        for (int ks = 0; ks < 2; ks++) {
            uint32_t kb = (uint32_t)(ks * 32);
            uint32_t ah[4][4], al[4][4];
#pragma unroll
            for (int mt = 0; mt < 4; mt++) {
                uint32_t o = aOff + mt * 16 * SSTRB + kb;
                ldsm_x4(ah[mt], uAh + o);
                ldsm_x4(al[mt], uAl + o);
            }
            uint32_t bh[2][4], bl[2][4];
#pragma unroll
            for (int p = 0; p < 2; p++) {
                uint32_t o = bOff + p * 16 * SSTRB + kb;
                ldsm_x4(bh[p], uBh + o);
                ldsm_x4(bl[p], uBl + o);
            }
#pragma unroll
            for (int mt = 0; mt < 4; mt++)
#pragma unroll
                for (int nt = 0; nt < 4; nt++) {
                    int p = nt >> 1, q = (nt & 1) * 2;
                    mma_bf16(acc[mt][nt], ah[mt], bh[p][q], bh[p][q + 1]);
                    mma_bf16(acc[mt][nt], ah[mt], bl[p][q], bl[p][q + 1]);
                    mma_bf16(acc[mt][nt], al[mt], bh[p][q], bh[p][q + 1]);
                }
        }
        __syncthreads();
    }

    // Epilogue
#pragma unroll
    for (int mt = 0; mt < 4; mt++)
#pragma unroll
        for (int nt = 0; nt < 4; nt++) {
            int row0 = rowBase + wm * 64 + mt * 16 + (lane >> 2);
            int col  = colBase + wn * 32 + nt * 8 + (lane & 3) * 2;
#pragma unroll
            for (int cp = 0; cp < 2; cp++) {
                int row = row0 + cp * 8;
                float v0 = acc[mt][nt][cp * 2], v1 = acc[mt][nt][cp * 2 + 1];
                if (MODE == 1) {
                    *(float2*)(outp + (size_t)row * D_MODEL + col) = make_float2(v0, v1);
                } else {
                    int z = blockIdx.z;
                    float sc = (z == 0) ? 0.125f : 1.0f;
                    v0 *= sc; v1 *= sc;
                    __nv_bfloat16* dh = (z == 0) ? g_Qh : (z == 1) ? g_Kh : g_Vh;
                    __nv_bfloat16* dl = (z == 0) ? g_Ql : (z == 1) ? g_Kl : g_Vl;
                    int b = row >> 11, s = row & 2047;
                    int h = col >> 6, d = col & 63;
                    size_t idx = ((size_t)(b * NUM_HEADS + h) * SEQ + s) * DK + d;
                    __nv_bfloat16 h0, h1;
                    uint32_t ph = split_pack_hi(v0, v1, h0, h1);
                    uint32_t pl = pack_bf16(__float2bfloat16(v0 - __bfloat162float(h0)),
                                            __float2bfloat16(v1 - __bfloat162float(h1)));
                    *(uint32_t*)(dh + idx) = ph;
                    *(uint32_t*)(dl + idx) = pl;
                }
            }
        }
}

// ---------------------------------------------------------------------------
// Flash attention on mma.sync (split-bf16, fp32 online softmax in frags).
// CTA: 128 q rows, 8 warps (16 q rows each), K-tile 64, dk=64.
// S = Qh*Kh + Qh*Kl + Ql*Kh ; O += Ph*Vh + Ph*Vl + Pl*Vh
// ---------------------------------------------------------------------------
#define FSTR  72                      // smem row stride (bf16)
#define FSTRB 144
#define FQ_ELE (128 * FSTR)           // 9216
#define FK_ELE (64 * FSTR)            // 4608
#define FL_SMEM ((2 * FQ_ELE + 4 * FK_ELE) * 2)   // 73728 bytes

__global__ __launch_bounds__(256) void flash_mma(const int* __restrict__ am)
{
    extern __shared__ __nv_bfloat16 sb[];
    __nv_bfloat16* sQh = sb;
    __nv_bfloat16* sQl = sb + FQ_ELE;
    __nv_bfloat16* sKh = sb + 2 * FQ_ELE;
    __nv_bfloat16* sKl = sb + 2 * FQ_ELE + FK_ELE;
    __nv_bfloat16* sVh = sb + 2 * FQ_ELE + 2 * FK_ELE;
    __nv_bfloat16* sVl = sb + 2 * FQ_ELE + 3 * FK_ELE;
    __shared__ int msk[64];

    int tid = threadIdx.x;
    int wid = tid >> 5, lane = tid & 31;
    int g = lane >> 2, tig = lane & 3;
    int q0 = blockIdx.x * 128;
    int h  = blockIdx.y;
    int b  = blockIdx.z;

    size_t hoff = ((size_t)(b * NUM_HEADS + h) * SEQ) * DK;
    const __nv_bfloat16* Qhg = g_Qh + hoff + (size_t)q0 * DK;
    const __nv_bfloat16* Qlg = g_Ql + hoff + (size_t)q0 * DK;

    // Load Q tiles (128 rows x 64, hi+lo)
#pragma unroll
    for (int u = 0; u < 4; u++) {
        int f = tid + 256 * u;
        int row = f >> 3, seg = (f & 7) * 8;
        *(uint4*)(sQh + row * FSTR + seg) = *(const uint4*)(Qhg + (size_t)row * DK + seg);
        *(uint4*)(sQl + row * FSTR + seg) = *(const uint4*)(Qlg + (size_t)row * DK + seg);
    }
    __syncthreads();

    // Q A-fragments (4 k-steps of 16 dk), hi and lo
    uint32_t uQh = smem_to_u32(sQh), uQl = smem_to_u32(sQl);
    uint32_t uKh = smem_to_u32(sKh), uKl = smem_to_u32(sKl);
    uint32_t uVh = smem_to_u32(sVh), uVl = smem_to_u32(sVl);
    uint32_t qOff = (uint32_t)((wid * 16 + (lane & 15)) * FSTRB + (lane >> 4) * 16);
    uint32_t qh[4][4], ql[4][4];
#pragma unroll
    for (int kst = 0; kst < 4; kst++) {
        ldsm_x4(qh[kst], uQh + qOff + kst * 32);
        ldsm_x4(ql[kst], uQl + qOff + kst * 32);
    }
    __syncthreads();   // Q frags in regs; smem Q region stays untouched anyway

    float oacc[8][4];
#pragma unroll
    for (int nt = 0; nt < 8; nt++)
#pragma unroll
        for (int c = 0; c < 4; c++) oacc[nt][c] = 0.f;
    float mrow[2] = {-1e30f, -1e30f}, lrow[2] = {0.f, 0.f};

    uint32_t bOffK = (uint32_t)(((lane & 7) + ((lane >> 4) & 1) * 8) * FSTRB + ((lane >> 3) & 1) * 16);
    uint32_t vOff  = (uint32_t)((lane & 15) * FSTRB + (lane >> 4) * 16);

    for (int k0 = 0; k0 < SEQ; k0 += 64) {
        // Load K/V tiles hi/lo (64 x 64 each)
        const __nv_bfloat16* Khg = g_Kh + hoff + (size_t)k0 * DK;
        const __nv_bfloat16* Klg = g_Kl + hoff + (size_t)k0 * DK;
        const __nv_bfloat16* Vhg = g_Vh + hoff + (size_t)k0 * DK;
        const __nv_bfloat16* Vlg = g_Vl + hoff + (size_t)k0 * DK;
#pragma unroll
        for (int u = 0; u < 2; u++) {
            int f = tid + 256 * u;
            int row = f >> 3, seg = (f & 7) * 8;
            int so = row * FSTR + seg;
            size_t go = (size_t)row * DK + seg;
            *(uint4*)(sKh + so) = *(const uint4*)(Khg + go);
            *(uint4*)(sKl + so) = *(const uint4*)(Klg + go);
            *(uint4*)(sVh + so) = *(const uint4*)(Vhg + go);
            *(uint4*)(sVl + so) = *(const uint4*)(Vlg + go);
        }
        if (tid < 64) msk[tid] = am[(size_t)b * SEQ + k0 + tid];
        __syncthreads();

        // ----- S = Q K^T (split, fp32 accum) -----
        float s[8][4];
#pragma unroll
        for (int nt = 0; nt < 8; nt++)
#pragma unroll
            for (int c = 0; c < 4; c++) s[nt][c] = 0.f;

#pragma unroll
        for (int p = 0; p < 4; p++) {
#pragma unroll
            for (int kst = 0; kst < 4; kst++) {
                uint32_t kh[4], kl[4];
                uint32_t o = p * 16 * FSTRB + kst * 32 + bOffK;
                ldsm_x4(kh, uKh + o);
                ldsm_x4(kl, uKl + o);
                int nt0 = 2 * p, nt1 = 2 * p + 1;
                mma_bf16(s[nt0], qh[kst], kh[0], kh[1]);
                mma_bf16(s[nt0], qh[kst], kl[0], kl[1]);
                mma_bf16(s[nt0], ql[kst], kh[0], kh[1]);
                mma_bf16(s[nt1], qh[kst], kh[2], kh[3]);
                mma_bf16(s[nt1], qh[kst], kl[2], kl[3]);
                mma_bf16(s[nt1], ql[kst], kh[2], kh[3]);
            }
        }

        // ----- mask -----
#pragma unroll
        for (int nt = 0; nt < 8; nt++) {
            int c0 = nt * 8 + tig * 2;
            if (msk[c0] == 0)     { s[nt][0] = -1e30f; s[nt][2] = -1e30f; }
            if (msk[c0 + 1] == 0) { s[nt][1] = -1e30f; s[nt][3] = -1e30f; }
        }

        // ----- online softmax (rows g and g+8) -----
        float mx0 = -1e30f, mx1 = -1e30f;
#pragma unroll
        for (int nt = 0; nt < 8; nt++) {
            mx0 = fmaxf(mx0, fmaxf(s[nt][0], s[nt][1]));
            mx1 = fmaxf(mx1, fmaxf(s[nt][2], s[nt][3]));
        }
#pragma unroll
        for (int o = 1; o <= 2; o <<= 1) {
            mx0 = fmaxf(mx0, __shfl_xor_sync(0xffffffffu, mx0, o));
            mx1 = fmaxf(mx1, __shfl_xor_sync(0xffffffffu, mx1, o));
        }
        float mn0 = fmaxf(mrow[0], mx0), mn1 = fmaxf(mrow[1], mx1);
        float al0 = __expf(mrow[0] - mn0), al1 = __expf(mrow[1] - mn1);
        float rs0 = 0.f, rs1 = 0.f;
#pragma unroll
        for (int nt = 0; nt < 8; nt++) {
            s[nt][0] = __expf(s[nt][0] - mn0); rs0 += s[nt][0];
            s[nt][1] = __expf(s[nt][1] - mn0); rs0 += s[nt][1];
            s[nt][2] = __expf(s[nt][2] - mn1); rs1 += s[nt][2];
            s[nt][3] = __expf(s[nt][3] - mn1); rs1 += s[nt][3];
        }
#pragma unroll
        for (int o = 1; o <= 2; o <<= 1) {
            rs0 += __shfl_xor_sync(0xffffffffu, rs0, o);
            rs1 += __shfl_xor_sync(0xffffffffu, rs1, o);
        }
        lrow[0] = lrow[0] * al0 + rs0;  mrow[0] = mn0;
        lrow[1] = lrow[1] * al1 + rs1;  mrow[1] = mn1;
#pragma unroll
        for (int nt = 0; nt < 8; nt++) {
            oacc[nt][0] *= al0; oacc[nt][1] *= al0;
            oacc[nt][2] *= al1; oacc[nt][3] *= al1;
        }

        // ----- P -> A-fragments (hi/lo), direct register conversion -----
        uint32_t pah[4][4], pal[4][4];
#pragma unroll
        for (int kc = 0; kc < 4; kc++) {
            const float* t0 = s[2 * kc];
            const float* t1 = s[2 * kc + 1];
            __nv_bfloat16 h0, h1;
            pah[kc][0] = split_pack_hi(t0[0], t0[1], h0, h1);
            pal[kc][0] = pack_bf16(__float2bfloat16(t0[0] - __bfloat162float(h0)),
                                   __float2bfloat16(t0[1] - __bfloat162float(h1)));
            pah[kc][1] = split_pack_hi(t0[2], t0[3], h0, h1);
            pal[kc][1] = pack_bf16(__float2bfloat16(t0[2] - __bfloat162float(h0)),
                                   __float2bfloat16(t0[3] - __bfloat162float(h1)));
            pah[kc][2] = split_pack_hi(t1[0], t1[1], h0, h1);
            pal[kc][2] = pack_bf16(__float2bfloat16(t1[0] - __bfloat162float(h0)),
                                   __float2bfloat16(t1[1] - __bfloat162float(h1)));
            pah[kc][3] = split_pack_hi(t1[2], t1[3], h0, h1);
            pal[kc][3] = pack_bf16(__float2bfloat16(t1[2] - __bfloat162float(h0)),
                                   __float2bfloat16(t1[3] - __bfloat162float(h1)));
        }

        // ----- O += P V (split) -----
#pragma unroll
        for (int kc = 0; kc < 4; kc++) {
            uint32_t vh[4][4], vl[4][4];
#pragma unroll
            for (int p = 0; p < 4; p++) {
                uint32_t o = kc * 16 * FSTRB + p * 32 + vOff;
                ldsm_x4_t(vh[p], uVh + o);
                ldsm_x4_t(vl[p], uVl + o);
            }
#pragma unroll
            for (int nt = 0; nt < 8; nt++) {
                int p = nt >> 1, q = (nt & 1) * 2;
                mma_bf16(oacc[nt], pah[kc], vh[p][q], vh[p][q + 1]);
                mma_bf16(oacc[nt], pah[kc], vl[p][q], vl[p][q + 1]);
                mma_bf16(oacc[nt], pal[kc], vh[p][q], vh[p][q + 1]);
            }
        }
        __syncthreads();
    }

    // ----- epilogue: normalize, split-bf16 write to g_AOh/g_AOl -----
    float inv0 = (lrow[0] > 0.f) ? (1.f / lrow[0]) : 0.f;
    float inv1 = (lrow[1] > 0.f) ? (1.f / lrow[1]) : 0.f;
    int r0 = q0 + wid * 16 + g;
    int r1 = r0 + 8;
#pragma unroll
    for (int nt = 0; nt < 8; nt++) {
        int d0 = nt * 8 + tig * 2;
        size_t i0 = ((size_t)b * SEQ + r0) * D_MODEL + h * DK + d0;
        size_t i1 = ((size_t)b * SEQ + r1) * D_MODEL + h * DK + d0;
        float v0 = oacc[nt][0] * inv0, v1 = oacc[nt][1] * inv0;
        float w0 = oacc[nt][2] * inv1, w1 = oacc[nt][3] * inv1;
        __nv_bfloat16 h0, h1;
        uint32_t ph = split_pack_hi(v0, v1, h0, h1);
        uint32_t pl = pack_bf16(__float2bfloat16(v0 - __bfloat162float(h0)),
                                __float2bfloat16(v1 - __bfloat162float(h1)));
        *(uint32_t*)(g_AOh + i0) = ph;
        *(uint32_t*)(g_AOl + i0) = pl;
        ph = split_pack_hi(w0, w1, h0, h1);
        pl = pack_bf16(__float2bfloat16(w0 - __bfloat162float(h0)),
                       __float2bfloat16(w1 - __bfloat162float(h1)));
        *(uint32_t*)(g_AOh + i1) = ph;
        *(uint32_t*)(g_AOl + i1) = pl;
    }
}

// ---------------------------------------------------------------------------
// Launch
// ---------------------------------------------------------------------------
extern "C" void kernel_launch(void* const* d_in, const int* in_sizes, int n_in,
                              void* d_out, int out_size)
{
    const float* x  = (const float*)d_in[0];
    const int*   am = (const int*)d_in[1];
    const float* Wq = (const float*)d_in[2];
    const float* Wk = (const float*)d_in[3];
    const float* Wv = (const float*)d_in[4];
    const float* Wo = (const float*)d_in[5];
    float* out = (float*)d_out;

    cudaFuncSetAttribute(flash_mma, cudaFuncAttributeMaxDynamicSharedMemorySize, FL_SMEM);

    dim3 gc(1024, 5);
    cvt_all<<<gc, 256>>>(x, Wq, Wk, Wv, Wo);

    dim3 gq(D_MODEL / 128, NROWS / 128, 3);     // (8, 32, 3)
    gemm_mma<0><<<gq, 256>>>(nullptr);

    dim3 ga(SEQ / 128, NUM_HEADS, BATCH);       // (16, 16, 2)
    flash_mma<<<ga, 256, FL_SMEM>>>(am);

    dim3 go(D_MODEL / 128, NROWS / 128, 1);     // (8, 32)
    gemm_mma<1><<<go, 256>>>(out);
}

// round 8
// speedup vs baseline: 2.7152x; 1.0927x over previous
#include <cuda_runtime.h>
#include <cuda_bf16.h>
#include <cstdint>
#include <math.h>

// Problem constants
#define D_MODEL   1024
#define NUM_HEADS 16
#define DK        64
#define BATCH     2
#define SEQ       2048
#define NROWS     (BATCH * SEQ)      // 4096
#define NX        (NROWS * D_MODEL)  // 4194304
#define NW        (D_MODEL * D_MODEL)// 1048576

// ---------------------------------------------------------------------------
// Scratch (device globals: allocation-free rule)
// ---------------------------------------------------------------------------
__device__ __nv_bfloat16 g_xh[NX],  g_xl[NX];         // x split hi/lo
__device__ __nv_bfloat16 g_Wh[4 * NW], g_Wl[4 * NW];  // Wq,Wk,Wv,Wo split
__device__ __nv_bfloat16 g_Qh[NX], g_Ql[NX];          // [b][h][s][d], pre-scaled 0.125
__device__ __nv_bfloat16 g_Kh[NX], g_Kl[NX];
__device__ __nv_bfloat16 g_Vh[NX], g_Vl[NX];
__device__ __nv_bfloat16 g_AOh[NX], g_AOl[NX];        // attn out split [b][s][h*64+d]

// ---------------------------------------------------------------------------
// PTX helpers (plain sm_100-safe: ldmatrix, mma.sync bf16, cp.async)
// ---------------------------------------------------------------------------
__device__ __forceinline__ uint32_t smem_to_u32(const void* p) {
    uint32_t a;
    asm("{ .reg .u64 t; cvta.to.shared.u64 t, %1; cvt.u32.u64 %0, t; }" : "=r"(a) : "l"(p));
    return a;
}
__device__ __forceinline__ void ldsm_x4(uint32_t* r, uint32_t addr) {
    asm volatile("ldmatrix.sync.aligned.m8n8.x4.shared.b16 {%0,%1,%2,%3}, [%4];"
        : "=r"(r[0]), "=r"(r[1]), "=r"(r[2]), "=r"(r[3]) : "r"(addr));
}
__device__ __forceinline__ void ldsm_x4_t(uint32_t* r, uint32_t addr) {
    asm volatile("ldmatrix.sync.aligned.m8n8.x4.trans.shared.b16 {%0,%1,%2,%3}, [%4];"
        : "=r"(r[0]), "=r"(r[1]), "=r"(r[2]), "=r"(r[3]) : "r"(addr));
}
__device__ __forceinline__ void mma_bf16(float* d, const uint32_t* a, uint32_t b0, uint32_t b1) {
    asm volatile("mma.sync.aligned.m16n8k16.row.col.f32.bf16.bf16.f32 "
        "{%0,%1,%2,%3}, {%4,%5,%6,%7}, {%8,%9}, {%0,%1,%2,%3};"
        : "+f"(d[0]), "+f"(d[1]), "+f"(d[2]), "+f"(d[3])
        : "r"(a[0]), "r"(a[1]), "r"(a[2]), "r"(a[3]), "r"(b0), "r"(b1));
}
__device__ __forceinline__ void cp16(uint32_t dst, const void* src) {
    asm volatile("cp.async.cg.shared.global [%0], [%1], 16;" :: "r"(dst), "l"(src));
}
__device__ __forceinline__ void cp4(uint32_t dst, const void* src) {
    asm volatile("cp.async.ca.shared.global [%0], [%1], 4;" :: "r"(dst), "l"(src));
}
#define CP_COMMIT() asm volatile("cp.async.commit_group;" ::: "memory")
#define CP_WAIT1()  asm volatile("cp.async.wait_group 1;" ::: "memory")
#define CP_WAIT0()  asm volatile("cp.async.wait_group 0;" ::: "memory")

__device__ __forceinline__ uint32_t pack_bf16(__nv_bfloat16 a, __nv_bfloat16 b) {
    __nv_bfloat162 t = __halves2bfloat162(a, b);
    return *(uint32_t*)&t;
}
__device__ __forceinline__ uint32_t split_pack_hi(float v0, float v1,
                                                  __nv_bfloat16& h0, __nv_bfloat16& h1) {
    h0 = __float2bfloat16(v0);
    h1 = __float2bfloat16(v1);
    return pack_bf16(h0, h1);
}

// ---------------------------------------------------------------------------
// Pre-pass: split-convert x + 4 weights to bf16 hi/lo (one shot)
// ---------------------------------------------------------------------------
__global__ __launch_bounds__(256) void cvt_all(
    const float* __restrict__ x,  const float* __restrict__ wq,
    const float* __restrict__ wk, const float* __restrict__ wv,
    const float* __restrict__ wo)
{
    int y = blockIdx.y;
    const float* s = (y == 0) ? x : (y == 1) ? wq : (y == 2) ? wk : (y == 3) ? wv : wo;
    __nv_bfloat16* dh = (y == 0) ? g_xh : g_Wh + (size_t)(y - 1) * NW;
    __nv_bfloat16* dl = (y == 0) ? g_xl : g_Wl + (size_t)(y - 1) * NW;
    size_t n = (y == 0) ? (size_t)NX : (size_t)NW;
    size_t stride = (size_t)gridDim.x * 256 * 4;
    for (size_t i = ((size_t)blockIdx.x * 256 + threadIdx.x) * 4; i < n; i += stride) {
        float4 v = *(const float4*)(s + i);
        float f[4] = {v.x, v.y, v.z, v.w};
        __nv_bfloat16 h[4], l[4];
#pragma unroll
        for (int e = 0; e < 4; e++) {
            h[e] = __float2bfloat16(f[e]);
            l[e] = __float2bfloat16(f[e] - __bfloat162float(h[e]));
        }
        *(uint2*)(dh + i) = make_uint2(pack_bf16(h[0], h[1]), pack_bf16(h[2], h[3]));
        *(uint2*)(dl + i) = make_uint2(pack_bf16(l[0], l[1]), pack_bf16(l[2], l[3]));
    }
}

// ---------------------------------------------------------------------------
// Split-bf16 tensor-core GEMM with cp.async 2-stage pipeline, 2 CTA/SM.
// C[4096x1024] = A @ W^T.  CTA 128x128, 8 warps (2m x 4n), k-stage 32.
// MODE 0: QKV (z selects W; epilogue -> bf16 hi/lo head-scatter, Q scaled)
// MODE 1: O-proj (A = g_AOh/l; fp32 epilogue to out)
// ---------------------------------------------------------------------------
#define SSTR 40                        // smem row stride in bf16
#define SSTRB 80
#define STAGE_ELE (128 * SSTR)         // 5120 bf16
#define STAGE_B   (STAGE_ELE * 2)      // 10240 bytes
#define GEMM_SMEM (8 * STAGE_B)        // 81920 bytes (4 arrays x 2 stages)

template<int MODE>
__global__ __launch_bounds__(256, 2) void gemm_mma(float* __restrict__ outp)
{
    extern __shared__ __nv_bfloat16 ds[];

    int tid = threadIdx.x;
    int wid = tid >> 5, lane = tid & 31;
    int wm = wid & 1, wn = wid >> 1;
    int rowBase = blockIdx.y * 128, colBase = blockIdx.x * 128;

    const __nv_bfloat16 *Ahg, *Alg, *Bhg, *Blg;
    if (MODE == 0) {
        int z = blockIdx.z;
        Ahg = g_xh;  Alg = g_xl;
        Bhg = g_Wh + (size_t)z * NW;  Blg = g_Wl + (size_t)z * NW;
    } else {
        Ahg = g_AOh; Alg = g_AOl;
        Bhg = g_Wh + 3ull * NW;       Blg = g_Wl + 3ull * NW;
    }
    Ahg += (size_t)rowBase * D_MODEL;  Alg += (size_t)rowBase * D_MODEL;
    Bhg += (size_t)colBase * D_MODEL;  Blg += (size_t)colBase * D_MODEL;

    uint32_t u0  = smem_to_u32(ds);
    uint32_t uAh = u0;
    uint32_t uAl = u0 + 2 * STAGE_B;
    uint32_t uBh = u0 + 4 * STAGE_B;
    uint32_t uBl = u0 + 6 * STAGE_B;

    float acc[4][4][4];
#pragma unroll
    for (int i = 0; i < 4; i++)
#pragma unroll
        for (int j = 0; j < 4; j++)
#pragma unroll
            for (int c = 0; c < 4; c++) acc[i][j][c] = 0.f;

    uint32_t aOff = (uint32_t)((wm * 64 + (lane & 15)) * SSTRB + (lane >> 4) * 16);
    uint32_t bOff = (uint32_t)((wn * 32 + (lane & 7) + ((lane >> 4) & 1) * 8) * SSTRB
                               + ((lane >> 3) & 1) * 16);

    auto issue = [&](int st) {
        uint32_t sb = (uint32_t)((st & 1) * STAGE_B);
        int k0 = st * 32;
#pragma unroll
        for (int u = 0; u < 2; u++) {
            int f = tid + 256 * u;
            int row = f >> 2, seg = (f & 3) * 8;
            uint32_t so = sb + (uint32_t)(row * SSTR + seg) * 2;
            size_t g = (size_t)row * D_MODEL + k0 + seg;
            cp16(uAh + so, Ahg + g);
            cp16(uAl + so, Alg + g);
            cp16(uBh + so, Bhg + g);
            cp16(uBl + so, Blg + g);
        }
        CP_COMMIT();
    };

    issue(0);

    for (int st = 0; st < D_MODEL / 32; st++) {
        uint32_t sOff = (uint32_t)((st & 1) * STAGE_B);
        if (st < D_MODEL / 32 - 1) { issue(st + 1); CP_WAIT1(); }
        else                       { CP_WAIT0(); }
        __syncthreads();

#pragma unroll
        for (int ks = 0; ks < 2; ks++) {
            uint32_t kb = (uint32_t)(ks * 32);
            uint32_t bh[2][4], bl[2][4];
#pragma unroll
            for (int p = 0; p < 2; p++) {
                uint32_t o = sOff + bOff + p * 16 * SSTRB + kb;
                ldsm_x4(bh[p], uBh + o);
                ldsm_x4(bl[p], uBl + o);
            }
#pragma unroll
            for (int mt = 0; mt < 4; mt++) {
                uint32_t ah[4], al[4];
                uint32_t o = sOff + aOff + mt * 16 * SSTRB + kb;
                ldsm_x4(ah, uAh + o);
                ldsm_x4(al, uAl + o);
#pragma unroll
                for (int nt = 0; nt < 4; nt++) {
                    int p = nt >> 1, q = (nt & 1) * 2;
                    mma_bf16(acc[mt][nt], ah, bh[p][q], bh[p][q + 1]);
                    mma_bf16(acc[mt][nt], ah, bl[p][q], bl[p][q + 1]);
                    mma_bf16(acc[mt][nt], al, bh[p][q], bh[p][q + 1]);
                }
            }
        }
        __syncthreads();
    }

    // Epilogue
#pragma unroll
    for (int mt = 0; mt < 4; mt++)
#pragma unroll
        for (int nt = 0; nt < 4; nt++) {
            int row0 = rowBase + wm * 64 + mt * 16 + (lane >> 2);
            int col  = colBase + wn * 32 + nt * 8 + (lane & 3) * 2;
#pragma unroll
            for (int cp = 0; cp < 2; cp++) {
                int row = row0 + cp * 8;
                float v0 = acc[mt][nt][cp * 2], v1 = acc[mt][nt][cp * 2 + 1];
                if (MODE == 1) {
                    *(float2*)(outp + (size_t)row * D_MODEL + col) = make_float2(v0, v1);
                } else {
                    int z = blockIdx.z;
                    float sc = (z == 0) ? 0.125f : 1.0f;
                    v0 *= sc; v1 *= sc;
                    __nv_bfloat16* dh = (z == 0) ? g_Qh : (z == 1) ? g_Kh : g_Vh;
                    __nv_bfloat16* dl = (z == 0) ? g_Ql : (z == 1) ? g_Kl : g_Vl;
                    int b = row >> 11, s = row & 2047;
                    int h = col >> 6, d = col & 63;
                    size_t idx = ((size_t)(b * NUM_HEADS + h) * SEQ + s) * DK + d;
                    __nv_bfloat16 h0, h1;
                    uint32_t ph = split_pack_hi(v0, v1, h0, h1);
                    uint32_t pl = pack_bf16(__float2bfloat16(v0 - __bfloat162float(h0)),
                                            __float2bfloat16(v1 - __bfloat162float(h1)));
                    *(uint32_t*)(dh + idx) = ph;
                    *(uint32_t*)(dl + idx) = pl;
                }
            }
        }
}

// ---------------------------------------------------------------------------
// Flash attention on mma.sync, cp.async 2-stage K/V pipeline.
// CTA: 128 q rows, 8 warps (16 q rows each), K-tile 64, dk=64.
// S = Qh*Kh + Qh*Kl + Ql*Kh ; O += Ph*Vh + Ph*Vl + Pl*Vh
// ---------------------------------------------------------------------------
#define FSTR  72                      // smem row stride (bf16)
#define FSTRB 144
#define FQ_ELE (128 * FSTR)           // 9216 bf16
#define FK_ELE (64 * FSTR)            // 4608 bf16
#define FKB    (FK_ELE * 2)           // 9216 bytes per stage per array
#define FL_SMEM ((2 * FQ_ELE + 8 * FK_ELE) * 2)   // 110592 bytes

__global__ __launch_bounds__(256) void flash_mma(const int* __restrict__ am)
{
    extern __shared__ __nv_bfloat16 sb[];
    __shared__ int msk[2][64];

    int tid = threadIdx.x;
    int wid = tid >> 5, lane = tid & 31;
    int g = lane >> 2, tig = lane & 3;
    int q0 = blockIdx.x * 128;
    int h  = blockIdx.y;
    int b  = blockIdx.z;

    size_t hoff = ((size_t)(b * NUM_HEADS + h) * SEQ) * DK;

    uint32_t uB  = smem_to_u32(sb);
    uint32_t uQh = uB;
    uint32_t uQl = uB + FQ_ELE * 2;
    uint32_t uKh = uB + 4 * FQ_ELE;          // bytes: 2 arrays * 9216 * 2 = 36864
    uint32_t uKl = uKh + 2 * FKB;
    uint32_t uVh = uKh + 4 * FKB;
    uint32_t uVl = uKh + 6 * FKB;
    uint32_t umsk = smem_to_u32(msk);

    const __nv_bfloat16* Khg = g_Kh + hoff;
    const __nv_bfloat16* Klg = g_Kl + hoff;
    const __nv_bfloat16* Vhg = g_Vh + hoff;
    const __nv_bfloat16* Vlg = g_Vl + hoff;

    auto issueKV = [&](int kt) {
        uint32_t sbyte = (uint32_t)((kt & 1) * FKB);
        size_t k0d = (size_t)(kt * 64) * DK;
#pragma unroll
        for (int u = 0; u < 2; u++) {
            int f = tid + 256 * u;
            int row = f >> 3, seg = (f & 7) * 8;
            uint32_t so = sbyte + (uint32_t)(row * FSTR + seg) * 2;
            size_t go = k0d + (size_t)row * DK + seg;
            cp16(uKh + so, Khg + go);
            cp16(uKl + so, Klg + go);
            cp16(uVh + so, Vhg + go);
            cp16(uVl + so, Vlg + go);
        }
        if (tid < 64)
            cp4(umsk + (uint32_t)(((kt & 1) * 64 + tid) * 4),
                am + (size_t)b * SEQ + kt * 64 + tid);
        CP_COMMIT();
    };

    // Kick off first K/V stage, then load Q behind it.
    issueKV(0);

    const __nv_bfloat16* Qhg = g_Qh + hoff + (size_t)q0 * DK;
    const __nv_bfloat16* Qlg = g_Ql + hoff + (size_t)q0 * DK;
#pragma unroll
    for (int u = 0; u < 4; u++) {
        int f = tid + 256 * u;
        int row = f >> 3, seg = (f & 7) * 8;
        *(uint4*)(sb + row * FSTR + seg) = *(const uint4*)(Qhg + (size_t)row * DK + seg);
        *(uint4*)(sb + FQ_ELE + row * FSTR + seg) = *(const uint4*)(Qlg + (size_t)row * DK + seg);
    }
    __syncthreads();

    uint32_t qOff = (uint32_t)((wid * 16 + (lane & 15)) * FSTRB + (lane >> 4) * 16);
    uint32_t qh[4][4], ql[4][4];
#pragma unroll
    for (int kst = 0; kst < 4; kst++) {
        ldsm_x4(qh[kst], uQh + qOff + kst * 32);
        ldsm_x4(ql[kst], uQl + qOff + kst * 32);
    }

    float oacc[8][4];
#pragma unroll
    for (int nt = 0; nt < 8; nt++)
#pragma unroll
        for (int c = 0; c < 4; c++) oacc[nt][c] = 0.f;
    float mrow[2] = {-1e30f, -1e30f}, lrow[2] = {0.f, 0.f};

    uint32_t bOffK = (uint32_t)(((lane & 7) + ((lane >> 4) & 1) * 8) * FSTRB + ((lane >> 3) & 1) * 16);
    uint32_t vOff  = (uint32_t)((lane & 15) * FSTRB + (lane >> 4) * 16);

    for (int kt = 0; kt < SEQ / 64; kt++) {
        int stage = kt & 1;
        if (kt < SEQ / 64 - 1) { issueKV(kt + 1); CP_WAIT1(); }
        else                   { CP_WAIT0(); }
        __syncthreads();

        uint32_t skh = uKh + stage * FKB, skl = uKl + stage * FKB;
        uint32_t svh = uVh + stage * FKB, svl = uVl + stage * FKB;

        // ----- S = Q K^T (split, fp32 accum) -----
        float s[8][4];
#pragma unroll
        for (int nt = 0; nt < 8; nt++)
#pragma unroll
            for (int c = 0; c < 4; c++) s[nt][c] = 0.f;

#pragma unroll
        for (int p = 0; p < 4; p++) {
#pragma unroll
            for (int kst = 0; kst < 4; kst++) {
                uint32_t kh[4], kl[4];
                uint32_t o = p * 16 * FSTRB + kst * 32 + bOffK;
                ldsm_x4(kh, skh + o);
                ldsm_x4(kl, skl + o);
                int nt0 = 2 * p, nt1 = 2 * p + 1;
                mma_bf16(s[nt0], qh[kst], kh[0], kh[1]);
                mma_bf16(s[nt0], qh[kst], kl[0], kl[1]);
                mma_bf16(s[nt0], ql[kst], kh[0], kh[1]);
                mma_bf16(s[nt1], qh[kst], kh[2], kh[3]);
                mma_bf16(s[nt1], qh[kst], kl[2], kl[3]);
                mma_bf16(s[nt1], ql[kst], kh[2], kh[3]);
            }
        }

        // ----- mask -----
#pragma unroll
        for (int nt = 0; nt < 8; nt++) {
            int c0 = nt * 8 + tig * 2;
            if (msk[stage][c0] == 0)     { s[nt][0] = -1e30f; s[nt][2] = -1e30f; }
            if (msk[stage][c0 + 1] == 0) { s[nt][1] = -1e30f; s[nt][3] = -1e30f; }
        }

        // ----- online softmax (rows g and g+8) -----
        float mx0 = -1e30f, mx1 = -1e30f;
#pragma unroll
        for (int nt = 0; nt < 8; nt++) {
            mx0 = fmaxf(mx0, fmaxf(s[nt][0], s[nt][1]));
            mx1 = fmaxf(mx1, fmaxf(s[nt][2], s[nt][3]));
        }
#pragma unroll
        for (int o = 1; o <= 2; o <<= 1) {
            mx0 = fmaxf(mx0, __shfl_xor_sync(0xffffffffu, mx0, o));
            mx1 = fmaxf(mx1, __shfl_xor_sync(0xffffffffu, mx1, o));
        }
        float mn0 = fmaxf(mrow[0], mx0), mn1 = fmaxf(mrow[1], mx1);
        float al0 = __expf(mrow[0] - mn0), al1 = __expf(mrow[1] - mn1);
        float rs0 = 0.f, rs1 = 0.f;
#pragma unroll
        for (int nt = 0; nt < 8; nt++) {
            s[nt][0] = __expf(s[nt][0] - mn0); rs0 += s[nt][0];
            s[nt][1] = __expf(s[nt][1] - mn0); rs0 += s[nt][1];
            s[nt][2] = __expf(s[nt][2] - mn1); rs1 += s[nt][2];
            s[nt][3] = __expf(s[nt][3] - mn1); rs1 += s[nt][3];
        }
#pragma unroll
        for (int o = 1; o <= 2; o <<= 1) {
            rs0 += __shfl_xor_sync(0xffffffffu, rs0, o);
            rs1 += __shfl_xor_sync(0xffffffffu, rs1, o);
        }
        lrow[0] = lrow[0] * al0 + rs0;  mrow[0] = mn0;
        lrow[1] = lrow[1] * al1 + rs1;  mrow[1] = mn1;
#pragma unroll
        for (int nt = 0; nt < 8; nt++) {
            oacc[nt][0] *= al0; oacc[nt][1] *= al0;
            oacc[nt][2] *= al1; oacc[nt][3] *= al1;
        }

        // ----- P -> A-fragments (hi/lo), direct register conversion -----
        uint32_t pah[4][4], pal[4][4];
#pragma unroll
        for (int kc = 0; kc < 4; kc++) {
            const float* t0 = s[2 * kc];
            const float* t1 = s[2 * kc + 1];
            __nv_bfloat16 h0, h1;
            pah[kc][0] = split_pack_hi(t0[0], t0[1], h0, h1);
            pal[kc][0] = pack_bf16(__float2bfloat16(t0[0] - __bfloat162float(h0)),
                                   __float2bfloat16(t0[1] - __bfloat162float(h1)));
            pah[kc][1] = split_pack_hi(t0[2], t0[3], h0, h1);
            pal[kc][1] = pack_bf16(__float2bfloat16(t0[2] - __bfloat162float(h0)),
                                   __float2bfloat16(t0[3] - __bfloat162float(h1)));
            pah[kc][2] = split_pack_hi(t1[0], t1[1], h0, h1);
            pal[kc][2] = pack_bf16(__float2bfloat16(t1[0] - __bfloat162float(h0)),
                                   __float2bfloat16(t1[1] - __bfloat162float(h1)));
            pah[kc][3] = split_pack_hi(t1[2], t1[3], h0, h1);
            pal[kc][3] = pack_bf16(__float2bfloat16(t1[2] - __bfloat162float(h0)),
                                   __float2bfloat16(t1[3] - __bfloat162float(h1)));
        }

        // ----- O += P V (split) -----
#pragma unroll
        for (int kc = 0; kc < 4; kc++) {
            uint32_t vh[4][4], vl[4][4];
#pragma unroll
            for (int p = 0; p < 4; p++) {
                uint32_t o = kc * 16 * FSTRB + p * 32 + vOff;
                ldsm_x4_t(vh[p], svh + o);
                ldsm_x4_t(vl[p], svl + o);
            }
#pragma unroll
            for (int nt = 0; nt < 8; nt++) {
                int p = nt >> 1, q = (nt & 1) * 2;
                mma_bf16(oacc[nt], pah[kc], vh[p][q], vh[p][q + 1]);
                mma_bf16(oacc[nt], pah[kc], vl[p][q], vl[p][q + 1]);
                mma_bf16(oacc[nt], pal[kc], vh[p][q], vh[p][q + 1]);
            }
        }
        __syncthreads();
    }

    // ----- epilogue: normalize, split-bf16 write to g_AOh/g_AOl -----
    float inv0 = (lrow[0] > 0.f) ? (1.f / lrow[0]) : 0.f;
    float inv1 = (lrow[1] > 0.f) ? (1.f / lrow[1]) : 0.f;
    int r0 = q0 + wid * 16 + g;
    int r1 = r0 + 8;
#pragma unroll
    for (int nt = 0; nt < 8; nt++) {
        int d0 = nt * 8 + tig * 2;
        size_t i0 = ((size_t)b * SEQ + r0) * D_MODEL + h * DK + d0;
        size_t i1 = ((size_t)b * SEQ + r1) * D_MODEL + h * DK + d0;
        float v0 = oacc[nt][0] * inv0, v1 = oacc[nt][1] * inv0;
        float w0 = oacc[nt][2] * inv1, w1 = oacc[nt][3] * inv1;
        __nv_bfloat16 h0, h1;
        uint32_t ph = split_pack_hi(v0, v1, h0, h1);
        uint32_t pl = pack_bf16(__float2bfloat16(v0 - __bfloat162float(h0)),
                                __float2bfloat16(v1 - __bfloat162float(h1)));
        *(uint32_t*)(g_AOh + i0) = ph;
        *(uint32_t*)(g_AOl + i0) = pl;
        ph = split_pack_hi(w0, w1, h0, h1);
        pl = pack_bf16(__float2bfloat16(w0 - __bfloat162float(h0)),
                       __float2bfloat16(w1 - __bfloat162float(h1)));
        *(uint32_t*)(g_AOh + i1) = ph;
        *(uint32_t*)(g_AOl + i1) = pl;
    }
}

// ---------------------------------------------------------------------------
// Launch
// ---------------------------------------------------------------------------
extern "C" void kernel_launch(void* const* d_in, const int* in_sizes, int n_in,
                              void* d_out, int out_size)
{
    const float* x  = (const float*)d_in[0];
    const int*   am = (const int*)d_in[1];
    const float* Wq = (const float*)d_in[2];
    const float* Wk = (const float*)d_in[3];
    const float* Wv = (const float*)d_in[4];
    const float* Wo = (const float*)d_in[5];
    float* out = (float*)d_out;

    cudaFuncSetAttribute(gemm_mma<0>, cudaFuncAttributeMaxDynamicSharedMemorySize, GEMM_SMEM);
    cudaFuncSetAttribute(gemm_mma<1>, cudaFuncAttributeMaxDynamicSharedMemorySize, GEMM_SMEM);
    cudaFuncSetAttribute(flash_mma, cudaFuncAttributeMaxDynamicSharedMemorySize, FL_SMEM);

    dim3 gc(1024, 5);
    cvt_all<<<gc, 256>>>(x, Wq, Wk, Wv, Wo);

    dim3 gq(D_MODEL / 128, NROWS / 128, 3);     // (8, 32, 3)
    gemm_mma<0><<<gq, 256, GEMM_SMEM>>>(nullptr);

    dim3 ga(SEQ / 128, NUM_HEADS, BATCH);       // (16, 16, 2)
    flash_mma<<<ga, 256, FL_SMEM>>>(am);

    dim3 go(D_MODEL / 128, NROWS / 128, 1);     // (8, 32)
    gemm_mma<1><<<go, 256, GEMM_SMEM>>>(out);
}

// round 10
// speedup vs baseline: 3.9256x; 1.4458x over previous
#include <cuda_runtime.h>
#include <cuda_fp16.h>
#include <cstdint>
#include <math.h>

// Problem constants
#define D_MODEL   1024
#define NUM_HEADS 16
#define DK        64
#define BATCH     2
#define SEQ       2048
#define NROWS     (BATCH * SEQ)      // 4096
#define NX        (NROWS * D_MODEL)  // 4194304
#define NW        (D_MODEL * D_MODEL)// 1048576

// ---------------------------------------------------------------------------
// Scratch (device globals: allocation-free rule)
// fp16 asymmetric split: "A" operands stored single, "B" operands hi+lo.
// ---------------------------------------------------------------------------
__device__ __half g_xh[NX];                        // x single fp16
__device__ __half g_Wh[4 * NW], g_Wl[4 * NW];      // Wq,Wk,Wv,Wo hi/lo
__device__ __half g_Qh[NX];                        // [b][h][s][d], pre-scaled 0.125
__device__ __half g_Kh[NX], g_Kl[NX];
__device__ __half g_Vh[NX], g_Vl[NX];
__device__ __half g_AOh[NX];                       // attn out single [b][s][h*64+d]

// ---------------------------------------------------------------------------
// PTX helpers (plain sm_100-safe: ldmatrix, mma.sync f16, cp.async)
// ---------------------------------------------------------------------------
__device__ __forceinline__ uint32_t smem_to_u32(const void* p) {
    uint32_t a;
    asm("{ .reg .u64 t; cvta.to.shared.u64 t, %1; cvt.u32.u64 %0, t; }" : "=r"(a) : "l"(p));
    return a;
}
__device__ __forceinline__ void ldsm_x4(uint32_t* r, uint32_t addr) {
    asm volatile("ldmatrix.sync.aligned.m8n8.x4.shared.b16 {%0,%1,%2,%3}, [%4];"
        : "=r"(r[0]), "=r"(r[1]), "=r"(r[2]), "=r"(r[3]) : "r"(addr));
}
__device__ __forceinline__ void ldsm_x4_t(uint32_t* r, uint32_t addr) {
    asm volatile("ldmatrix.sync.aligned.m8n8.x4.trans.shared.b16 {%0,%1,%2,%3}, [%4];"
        : "=r"(r[0]), "=r"(r[1]), "=r"(r[2]), "=r"(r[3]) : "r"(addr));
}
__device__ __forceinline__ void mma_f16(float* d, const uint32_t* a, uint32_t b0, uint32_t b1) {
    asm volatile("mma.sync.aligned.m16n8k16.row.col.f32.f16.f16.f32 "
        "{%0,%1,%2,%3}, {%4,%5,%6,%7}, {%8,%9}, {%0,%1,%2,%3};"
        : "+f"(d[0]), "+f"(d[1]), "+f"(d[2]), "+f"(d[3])
        : "r"(a[0]), "r"(a[1]), "r"(a[2]), "r"(a[3]), "r"(b0), "r"(b1));
}
__device__ __forceinline__ void cp16(uint32_t dst, const void* src) {
    asm volatile("cp.async.cg.shared.global [%0], [%1], 16;" :: "r"(dst), "l"(src));
}
__device__ __forceinline__ void cp4(uint32_t dst, const void* src) {
    asm volatile("cp.async.ca.shared.global [%0], [%1], 4;" :: "r"(dst), "l"(src));
}
#define CP_COMMIT() asm volatile("cp.async.commit_group;" ::: "memory")
#define CP_WAIT0()  asm volatile("cp.async.wait_group 0;" ::: "memory")

__device__ __forceinline__ uint32_t pack_h(__half a, __half b) {
    __half2 t = __halves2half2(a, b);
    return *(uint32_t*)&t;
}

// ---------------------------------------------------------------------------
// Pre-pass: convert x (single fp16) + 4 weights (fp16 hi/lo)
// ---------------------------------------------------------------------------
__global__ __launch_bounds__(256) void cvt_all(
    const float* __restrict__ x,  const float* __restrict__ wq,
    const float* __restrict__ wk, const float* __restrict__ wv,
    const float* __restrict__ wo)
{
    int y = blockIdx.y;
    const float* s = (y == 0) ? x : (y == 1) ? wq : (y == 2) ? wk : (y == 3) ? wv : wo;
    __half* dh = (y == 0) ? g_xh : g_Wh + (size_t)(y - 1) * NW;
    __half* dl = (y == 0) ? (__half*)nullptr : g_Wl + (size_t)(y - 1) * NW;
    size_t n = (y == 0) ? (size_t)NX : (size_t)NW;
    size_t stride = (size_t)gridDim.x * 256 * 4;
    for (size_t i = ((size_t)blockIdx.x * 256 + threadIdx.x) * 4; i < n; i += stride) {
        float4 v = *(const float4*)(s + i);
        float f[4] = {v.x, v.y, v.z, v.w};
        __half h[4];
#pragma unroll
        for (int e = 0; e < 4; e++) h[e] = __float2half_rn(f[e]);
        *(uint2*)(dh + i) = make_uint2(pack_h(h[0], h[1]), pack_h(h[2], h[3]));
        if (y != 0) {
            __half l[4];
#pragma unroll
            for (int e = 0; e < 4; e++)
                l[e] = __float2half_rn(f[e] - __half2float(h[e]));
            *(uint2*)(dl + i) = make_uint2(pack_h(l[0], l[1]), pack_h(l[2], l[3]));
        }
    }
}

// ---------------------------------------------------------------------------
// fp16 asymmetric-split GEMM: C = A(single) @ (Wh + Wl)^T, 2 mma per tile-k16.
// CTA 128x128, 8 warps (2m x 4n), k-stage 32, cp.async 2-stage, 1 sync/stage.
// MODE 0: QKV (z selects W; epilogue: Q -> single (x0.125), K/V -> hi+lo)
// MODE 1: O-proj (A = g_AOh; fp32 epilogue to out)
// ---------------------------------------------------------------------------
#define SSTR 40                        // smem row stride in halves
#define SSTRB 80
#define STAGE_B   (128 * SSTR * 2)     // 10240 bytes per array per stage
#define GEMM_SMEM (6 * STAGE_B)        // 61440: A(2 stages) + Bh(2) + Bl(2)

template<int MODE>
__global__ __launch_bounds__(256, 2) void gemm_mma(float* __restrict__ outp)
{
    extern __shared__ __half ds[];

    int tid = threadIdx.x;
    int wid = tid >> 5, lane = tid & 31;
    int wm = wid & 1, wn = wid >> 1;
    int rowBase = blockIdx.y * 128, colBase = blockIdx.x * 128;

    const __half *Ag, *Bhg, *Blg;
    if (MODE == 0) {
        int z = blockIdx.z;
        Ag = g_xh;
        Bhg = g_Wh + (size_t)z * NW;  Blg = g_Wl + (size_t)z * NW;
    } else {
        Ag = g_AOh;
        Bhg = g_Wh + 3ull * NW;       Blg = g_Wl + 3ull * NW;
    }
    Ag  += (size_t)rowBase * D_MODEL;
    Bhg += (size_t)colBase * D_MODEL;  Blg += (size_t)colBase * D_MODEL;

    uint32_t u0  = smem_to_u32(ds);
    uint32_t uA  = u0;
    uint32_t uBh = u0 + 2 * STAGE_B;
    uint32_t uBl = u0 + 4 * STAGE_B;

    float acc[4][4][4];
#pragma unroll
    for (int i = 0; i < 4; i++)
#pragma unroll
        for (int j = 0; j < 4; j++)
#pragma unroll
            for (int c = 0; c < 4; c++) acc[i][j][c] = 0.f;

    uint32_t aOff = (uint32_t)((wm * 64 + (lane & 15)) * SSTRB + (lane >> 4) * 16);
    uint32_t bOff = (uint32_t)((wn * 32 + (lane & 7) + ((lane >> 4) & 1) * 8) * SSTRB
                               + ((lane >> 3) & 1) * 16);

    auto issue = [&](int st) {
        uint32_t sb = (uint32_t)((st & 1) * STAGE_B);
        int k0 = st * 32;
#pragma unroll
        for (int u = 0; u < 2; u++) {
            int f = tid + 256 * u;
            int row = f >> 2, seg = (f & 3) * 8;
            uint32_t so = sb + (uint32_t)(row * SSTR + seg) * 2;
            size_t g = (size_t)row * D_MODEL + k0 + seg;
            cp16(uA  + so, Ag  + g);
            cp16(uBh + so, Bhg + g);
            cp16(uBl + so, Blg + g);
        }
        CP_COMMIT();
    };

    issue(0);

    for (int st = 0; st < D_MODEL / 32; st++) {
        uint32_t sOff = (uint32_t)((st & 1) * STAGE_B);
        CP_WAIT0();
        __syncthreads();          // stage st visible; all warps done with buffer st-1
        if (st < D_MODEL / 32 - 1) issue(st + 1);

#pragma unroll
        for (int ks = 0; ks < 2; ks++) {
            uint32_t kb = (uint32_t)(ks * 32);
            uint32_t bh[2][4], bl[2][4];
#pragma unroll
            for (int p = 0; p < 2; p++) {
                uint32_t o = sOff + bOff + p * 16 * SSTRB + kb;
                ldsm_x4(bh[p], uBh + o);
                ldsm_x4(bl[p], uBl + o);
            }
#pragma unroll
            for (int mt = 0; mt < 4; mt++) {
                uint32_t ah[4];
                ldsm_x4(ah, uA + sOff + aOff + mt * 16 * SSTRB + kb);
#pragma unroll
                for (int nt = 0; nt < 4; nt++) {
                    int p = nt >> 1, q = (nt & 1) * 2;
                    mma_f16(acc[mt][nt], ah, bh[p][q], bh[p][q + 1]);
                    mma_f16(acc[mt][nt], ah, bl[p][q], bl[p][q + 1]);
                }
            }
        }
    }

    // Epilogue
#pragma unroll
    for (int mt = 0; mt < 4; mt++)
#pragma unroll
        for (int nt = 0; nt < 4; nt++) {
            int row0 = rowBase + wm * 64 + mt * 16 + (lane >> 2);
            int col  = colBase + wn * 32 + nt * 8 + (lane & 3) * 2;
#pragma unroll
            for (int cp = 0; cp < 2; cp++) {
                int row = row0 + cp * 8;
                float v0 = acc[mt][nt][cp * 2], v1 = acc[mt][nt][cp * 2 + 1];
                if (MODE == 1) {
                    *(float2*)(outp + (size_t)row * D_MODEL + col) = make_float2(v0, v1);
                } else {
                    int z = blockIdx.z;
                    if (z == 0) { v0 *= 0.125f; v1 *= 0.125f; }
                    int b = row >> 11, s = row & 2047;
                    int h = col >> 6, d = col & 63;
                    size_t idx = ((size_t)(b * NUM_HEADS + h) * SEQ + s) * DK + d;
                    __half h0 = __float2half_rn(v0), h1 = __float2half_rn(v1);
                    __half* dh = (z == 0) ? g_Qh : (z == 1) ? g_Kh : g_Vh;
                    *(uint32_t*)(dh + idx) = pack_h(h0, h1);
                    if (z != 0) {
                        __half* dl = (z == 1) ? g_Kl : g_Vl;
                        __half l0 = __float2half_rn(v0 - __half2float(h0));
                        __half l1 = __float2half_rn(v1 - __half2float(h1));
                        *(uint32_t*)(dl + idx) = pack_h(l0, l1);
                    }
                }
            }
        }
}

// ---------------------------------------------------------------------------
// Flash attention, fp16 asymmetric split:
//   S = Qh*(Kh+Kl)  (Q single, 2 mma);  O += Ph*(Vh+Vl)  (P single, 2 mma)
// CTA: 128 q rows, 8 warps, K-tile 64, cp.async 2-stage K/V, 1 sync/tile.
// ---------------------------------------------------------------------------
#define FSTR  72                      // smem row stride (halves)
#define FSTRB 144
#define FQ_ELE (128 * FSTR)           // 9216 halves
#define FQB    (FQ_ELE * 2)           // 18432 bytes
#define FK_ELE (64 * FSTR)            // 4608 halves
#define FKB    (FK_ELE * 2)           // 9216 bytes per array per stage
#define FL_SMEM (FQB + 8 * FKB)       // 92160 bytes

__global__ __launch_bounds__(256) void flash_mma(const int* __restrict__ am)
{
    extern __shared__ __half sb[];
    __shared__ int msk[2][64];

    int tid = threadIdx.x;
    int wid = tid >> 5, lane = tid & 31;
    int g = lane >> 2, tig = lane & 3;
    int q0 = blockIdx.x * 128;
    int h  = blockIdx.y;
    int b  = blockIdx.z;

    size_t hoff = ((size_t)(b * NUM_HEADS + h) * SEQ) * DK;

    uint32_t uB  = smem_to_u32(sb);
    uint32_t uQ  = uB;
    uint32_t uKh = uB + FQB;
    uint32_t uKl = uKh + 2 * FKB;
    uint32_t uVh = uKh + 4 * FKB;
    uint32_t uVl = uKh + 6 * FKB;
    uint32_t umsk = smem_to_u32(msk);

    const __half* Khg = g_Kh + hoff;
    const __half* Klg = g_Kl + hoff;
    const __half* Vhg = g_Vh + hoff;
    const __half* Vlg = g_Vl + hoff;

    auto issueKV = [&](int kt) {
        uint32_t sbyte = (uint32_t)((kt & 1) * FKB);
        size_t k0d = (size_t)(kt * 64) * DK;
#pragma unroll
        for (int u = 0; u < 2; u++) {
            int f = tid + 256 * u;
            int row = f >> 3, seg = (f & 7) * 8;
            uint32_t so = sbyte + (uint32_t)(row * FSTR + seg) * 2;
            size_t go = k0d + (size_t)row * DK + seg;
            cp16(uKh + so, Khg + go);
            cp16(uKl + so, Klg + go);
            cp16(uVh + so, Vhg + go);
            cp16(uVl + so, Vlg + go);
        }
        if (tid < 64)
            cp4(umsk + (uint32_t)(((kt & 1) * 64 + tid) * 4),
                am + (size_t)b * SEQ + kt * 64 + tid);
        CP_COMMIT();
    };

    issueKV(0);

    // Load Q (single fp16, 128 rows x 64 halves) behind the first K/V fetch.
    // 256 threads: row = tid>>1 (0..127), seg = (tid&1)*32 -> full tile, no overrun.
    const __half* Qg = g_Qh + hoff + (size_t)q0 * DK;
    {
        int row = tid >> 1, seg = (tid & 1) * 32;
        *(uint4*)(sb + row * FSTR + seg)      = *(const uint4*)(Qg + (size_t)row * DK + seg);
        *(uint4*)(sb + row * FSTR + seg + 8)  = *(const uint4*)(Qg + (size_t)row * DK + seg + 8);
        *(uint4*)(sb + row * FSTR + seg + 16) = *(const uint4*)(Qg + (size_t)row * DK + seg + 16);
        *(uint4*)(sb + row * FSTR + seg + 24) = *(const uint4*)(Qg + (size_t)row * DK + seg + 24);
    }
    __syncthreads();

    uint32_t qOff = (uint32_t)((wid * 16 + (lane & 15)) * FSTRB + (lane >> 4) * 16);
    uint32_t qh[4][4];
#pragma unroll
    for (int kst = 0; kst < 4; kst++)
        ldsm_x4(qh[kst], uQ + qOff + kst * 32);

    float oacc[8][4];
#pragma unroll
    for (int nt = 0; nt < 8; nt++)
#pragma unroll
        for (int c = 0; c < 4; c++) oacc[nt][c] = 0.f;
    float mrow[2] = {-1e30f, -1e30f}, lrow[2] = {0.f, 0.f};

    uint32_t bOffK = (uint32_t)(((lane & 7) + ((lane >> 4) & 1) * 8) * FSTRB + ((lane >> 3) & 1) * 16);
    uint32_t vOff  = (uint32_t)((lane & 15) * FSTRB + (lane >> 4) * 16);

    for (int kt = 0; kt < SEQ / 64; kt++) {
        int stage = kt & 1;
        CP_WAIT0();
        __syncthreads();          // stage kt visible; all warps done with buffer kt-1
        if (kt < SEQ / 64 - 1) issueKV(kt + 1);

        uint32_t skh = uKh + stage * FKB, skl = uKl + stage * FKB;
        uint32_t svh = uVh + stage * FKB, svl = uVl + stage * FKB;

        // ----- S = Qh (Kh + Kl)^T -----
        float s[8][4];
#pragma unroll
        for (int nt = 0; nt < 8; nt++)
#pragma unroll
            for (int c = 0; c < 4; c++) s[nt][c] = 0.f;

#pragma unroll
        for (int p = 0; p < 4; p++) {
#pragma unroll
            for (int kst = 0; kst < 4; kst++) {
                uint32_t kh[4], kl[4];
                uint32_t o = p * 16 * FSTRB + kst * 32 + bOffK;
                ldsm_x4(kh, skh + o);
                ldsm_x4(kl, skl + o);
                int nt0 = 2 * p, nt1 = 2 * p + 1;
                mma_f16(s[nt0], qh[kst], kh[0], kh[1]);
                mma_f16(s[nt0], qh[kst], kl[0], kl[1]);
                mma_f16(s[nt1], qh[kst], kh[2], kh[3]);
                mma_f16(s[nt1], qh[kst], kl[2], kl[3]);
            }
        }

        // ----- mask -----
#pragma unroll
        for (int nt = 0; nt < 8; nt++) {
            int c0 = nt * 8 + tig * 2;
            if (msk[stage][c0] == 0)     { s[nt][0] = -1e30f; s[nt][2] = -1e30f; }
            if (msk[stage][c0 + 1] == 0) { s[nt][1] = -1e30f; s[nt][3] = -1e30f; }
        }

        // ----- online softmax (rows g and g+8) -----
        float mx0 = -1e30f, mx1 = -1e30f;
#pragma unroll
        for (int nt = 0; nt < 8; nt++) {
            mx0 = fmaxf(mx0, fmaxf(s[nt][0], s[nt][1]));
            mx1 = fmaxf(mx1, fmaxf(s[nt][2], s[nt][3]));
        }
#pragma unroll
        for (int o = 1; o <= 2; o <<= 1) {
            mx0 = fmaxf(mx0, __shfl_xor_sync(0xffffffffu, mx0, o));
            mx1 = fmaxf(mx1, __shfl_xor_sync(0xffffffffu, mx1, o));
        }
        float mn0 = fmaxf(mrow[0], mx0), mn1 = fmaxf(mrow[1], mx1);
        float al0 = __expf(mrow[0] - mn0), al1 = __expf(mrow[1] - mn1);
        float rs0 = 0.f, rs1 = 0.f;
#pragma unroll
        for (int nt = 0; nt < 8; nt++) {
            s[nt][0] = __expf(s[nt][0] - mn0); rs0 += s[nt][0];
            s[nt][1] = __expf(s[nt][1] - mn0); rs0 += s[nt][1];
            s[nt][2] = __expf(s[nt][2] - mn1); rs1 += s[nt][2];
            s[nt][3] = __expf(s[nt][3] - mn1); rs1 += s[nt][3];
        }
#pragma unroll
        for (int o = 1; o <= 2; o <<= 1) {
            rs0 += __shfl_xor_sync(0xffffffffu, rs0, o);
            rs1 += __shfl_xor_sync(0xffffffffu, rs1, o);
        }
        lrow[0] = lrow[0] * al0 + rs0;  mrow[0] = mn0;
        lrow[1] = lrow[1] * al1 + rs1;  mrow[1] = mn1;
#pragma unroll
        for (int nt = 0; nt < 8; nt++) {
            oacc[nt][0] *= al0; oacc[nt][1] *= al0;
            oacc[nt][2] *= al1; oacc[nt][3] *= al1;
        }

        // ----- P -> single-fp16 A-fragments -----
        uint32_t pa[4][4];
#pragma unroll
        for (int kc = 0; kc < 4; kc++) {
            const float* t0 = s[2 * kc];
            const float* t1 = s[2 * kc + 1];
            pa[kc][0] = pack_h(__float2half_rn(t0[0]), __float2half_rn(t0[1]));
            pa[kc][1] = pack_h(__float2half_rn(t0[2]), __float2half_rn(t0[3]));
            pa[kc][2] = pack_h(__float2half_rn(t1[0]), __float2half_rn(t1[1]));
            pa[kc][3] = pack_h(__float2half_rn(t1[2]), __float2half_rn(t1[3]));
        }

        // ----- O += P (Vh + Vl) -----
#pragma unroll
        for (int kc = 0; kc < 4; kc++) {
            uint32_t vh[4][4], vl[4][4];
#pragma unroll
            for (int p = 0; p < 4; p++) {
                uint32_t o = kc * 16 * FSTRB + p * 32 + vOff;
                ldsm_x4_t(vh[p], svh + o);
                ldsm_x4_t(vl[p], svl + o);
            }
#pragma unroll
            for (int nt = 0; nt < 8; nt++) {
                int p = nt >> 1, q = (nt & 1) * 2;
                mma_f16(oacc[nt], pa[kc], vh[p][q], vh[p][q + 1]);
                mma_f16(oacc[nt], pa[kc], vl[p][q], vl[p][q + 1]);
            }
        }
    }

    // ----- epilogue: normalize, single-fp16 write to g_AOh -----
    float inv0 = (lrow[0] > 0.f) ? (1.f / lrow[0]) : 0.f;
    float inv1 = (lrow[1] > 0.f) ? (1.f / lrow[1]) : 0.f;
    int r0 = q0 + wid * 16 + g;
    int r1 = r0 + 8;
#pragma unroll
    for (int nt = 0; nt < 8; nt++) {
        int d0 = nt * 8 + tig * 2;
        size_t i0 = ((size_t)b * SEQ + r0) * D_MODEL + h * DK + d0;
        size_t i1 = ((size_t)b * SEQ + r1) * D_MODEL + h * DK + d0;
        *(uint32_t*)(g_AOh + i0) = pack_h(__float2half_rn(oacc[nt][0] * inv0),
                                          __float2half_rn(oacc[nt][1] * inv0));
        *(uint32_t*)(g_AOh + i1) = pack_h(__float2half_rn(oacc[nt][2] * inv1),
                                          __float2half_rn(oacc[nt][3] * inv1));
    }
}

// ---------------------------------------------------------------------------
// Launch
// ---------------------------------------------------------------------------
extern "C" void kernel_launch(void* const* d_in, const int* in_sizes, int n_in,
                              void* d_out, int out_size)
{
    const float* x  = (const float*)d_in[0];
    const int*   am = (const int*)d_in[1];
    const float* Wq = (const float*)d_in[2];
    const float* Wk = (const float*)d_in[3];
    const float* Wv = (const float*)d_in[4];
    const float* Wo = (const float*)d_in[5];
    float* out = (float*)d_out;

    cudaFuncSetAttribute(gemm_mma<0>, cudaFuncAttributeMaxDynamicSharedMemorySize, GEMM_SMEM);
    cudaFuncSetAttribute(gemm_mma<1>, cudaFuncAttributeMaxDynamicSharedMemorySize, GEMM_SMEM);
    cudaFuncSetAttribute(flash_mma, cudaFuncAttributeMaxDynamicSharedMemorySize, FL_SMEM);

    dim3 gc(1024, 5);
    cvt_all<<<gc, 256>>>(x, Wq, Wk, Wv, Wo);

    dim3 gq(D_MODEL / 128, NROWS / 128, 3);     // (8, 32, 3)
    gemm_mma<0><<<gq, 256, GEMM_SMEM>>>(nullptr);

    dim3 ga(SEQ / 128, NUM_HEADS, BATCH);       // (16, 16, 2)
    flash_mma<<<ga, 256, FL_SMEM>>>(am);

    dim3 go(D_MODEL / 128, NROWS / 128, 1);     // (8, 32)
    gemm_mma<1><<<go, 256, GEMM_SMEM>>>(out);
}